// round 15
// baseline (speedup 1.0000x reference)
#include <cuda_runtime.h>
#include <cuda_bf16.h>
#include <math.h>
#include <stdint.h>

#define Bb 8
#define Ss 512
#define Hh 1024
#define Ee 8
#define NHEAD 8
#define HD 64
#define HSUB 512
#define INTER 1536
#define NPAIR 16
#define QKVW 1536
#define GUW 3072

// ---------------- scratch ----------------
__device__ float g_h[Bb * Ss * Hh];
__device__ float g_hs[NPAIR * Ss * HSUB];
__device__ float g_qkv[NPAIR * Ss * QKVW];
__device__ float g_tmp[NPAIR * Ss * HSUB];
__device__ float g_up[NPAIR * Ss * Hh];
__device__ int   g_pair_e[NPAIR];
__device__ float g_pair_w[NPAIR];

#define OFF_DOWN 0L
#define OFF_QKV  4194304L
#define OFF_O    10485760L
#define OFF_GU   12582912L
#define OFF_MLPD 25165824L
#define OFF_UP   31457280L
#define W_TOTAL  35651584L
__device__ unsigned short g_wh[W_TOTAL];
__device__ unsigned short g_wl[W_TOTAL];
__device__ unsigned short g_p0h[NPAIR * Ss * INTER];
__device__ unsigned short g_p0l[NPAIR * Ss * INTER];
__device__ unsigned short g_p1h[NPAIR * Ss * INTER];
__device__ unsigned short g_p1l[NPAIR * Ss * INTER];
#define AWP 4194304L
__device__ unsigned short g_aw[6 * AWP];
#define WQH 0L
#define WQL (1*AWP)
#define WKH (2*AWP)
#define WKL (3*AWP)
#define WVH (4*AWP)
#define WVL (5*AWP)

// ---------------- PTX helpers ----------------
__device__ __forceinline__ uint32_t smem_u32(const void* p) {
    uint32_t a;
    asm("{ .reg .u64 t; cvta.to.shared.u64 t, %1; cvt.u32.u64 %0, t; }" : "=r"(a) : "l"(p));
    return a;
}
#define CP_ASYNC(sm, gp) asm volatile("cp.async.cg.shared.global [%0], [%1], 16;" :: "r"(sm), "l"(gp))
#define CP_COMMIT()      asm volatile("cp.async.commit_group;" ::: "memory")
#define CP_WAIT1()       asm volatile("cp.async.wait_group 1;" ::: "memory")
#define LDMX4(r0, r1, r2, r3, a) \
    asm volatile("ldmatrix.sync.aligned.m8n8.x4.shared.b16 {%0,%1,%2,%3}, [%4];" \
        : "=r"(r0), "=r"(r1), "=r"(r2), "=r"(r3) : "r"(a))
#define MMA16816(d, a0, a1, a2, a3, b0, b1) \
    asm volatile("mma.sync.aligned.m16n8k16.row.col.f32.bf16.bf16.f32 " \
        "{%0,%1,%2,%3}, {%4,%5,%6,%7}, {%8,%9}, {%0,%1,%2,%3};" \
        : "+f"((d)[0]), "+f"((d)[1]), "+f"((d)[2]), "+f"((d)[3]) \
        : "r"(a0), "r"(a1), "r"(a2), "r"(a3), "r"(b0), "r"(b1))

__device__ __forceinline__ void split2(float x, unsigned short& h, unsigned short& l) {
    __nv_bfloat16 hb = __float2bfloat16(x);
    h = __bfloat16_as_ushort(hb);
    l = __bfloat16_as_ushort(__float2bfloat16(x - __bfloat162float(hb)));
}

// ---------------- h = hidden + injection, fused hi/lo split ----------------
__global__ void add3_kernel(const float* __restrict__ a, const float* __restrict__ b,
                            unsigned short* __restrict__ hi, unsigned short* __restrict__ lo) {
    long i = (long)blockIdx.x * 256 + threadIdx.x;
    float4 va = ((const float4*)a)[i];
    float4 vb = ((const float4*)b)[i];
    float x[4] = {va.x + vb.x, va.y + vb.y, va.z + vb.z, va.w + vb.w};
    ((float4*)g_h)[i] = make_float4(x[0], x[1], x[2], x[3]);
    unsigned int h[4], l[4];
#pragma unroll
    for (int j = 0; j < 4; j++) { unsigned short hs_, ls_; split2(x[j], hs_, ls_); h[j] = hs_; l[j] = ls_; }
    uint2 uh, ul;
    uh.x = h[0] | (h[1] << 16); uh.y = h[2] | (h[3] << 16);
    ul.x = l[0] | (l[1] << 16); ul.y = l[2] | (l[3] << 16);
    ((uint2*)hi)[i] = uh; ((uint2*)lo)[i] = ul;
}

// ---------------- all weights -> 2 bf16 planes; gate_up rows interleaved ----------------
__global__ void cvtw_kernel(const float* __restrict__ p0, const float* __restrict__ p1,
                            const float* __restrict__ p2, const float* __restrict__ p3,
                            const float* __restrict__ p4, const float* __restrict__ p5,
                            unsigned short* __restrict__ hi, unsigned short* __restrict__ lo) {
    long i = (long)blockIdx.x * 256 + threadIdx.x;   // float4 index, total 8912896
    const float* src; long off;
    if (i < 1048576L)      { src = p0; off = 0L; }
    else if (i < 2621440L) { src = p1; off = 1048576L; }
    else if (i < 3145728L) { src = p2; off = 2621440L; }
    else if (i < 6291456L) { src = p3; off = 3145728L; }
    else if (i < 7864320L) { src = p4; off = 6291456L; }
    else                   { src = p5; off = 7864320L; }
    float4 v = ((const float4*)src)[i - off];
    float x[4] = {v.x, v.y, v.z, v.w};
    unsigned int h[4], l[4];
#pragma unroll
    for (int j = 0; j < 4; j++) { unsigned short hs_, ls_; split2(x[j], hs_, ls_); h[j] = hs_; l[j] = ls_; }
    uint2 uh, ul;
    uh.x = h[0] | (h[1] << 16); uh.y = h[2] | (h[3] << 16);
    ul.x = l[0] | (l[1] << 16); ul.y = l[2] | (l[3] << 16);
    long di = i;
    if (i >= 3145728L && i < 6291456L) {
        long idx4 = i - 3145728L;
        long exp_ = idx4 / 393216L;
        long rem = idx4 - exp_ * 393216L;
        long row = rem >> 7;
        long col4 = rem & 127;
        long nrow = (row < 1536) ? 2 * row : 2 * (row - 1536) + 1;
        di = 3145728L + exp_ * 393216L + nrow * 128 + col4;
    }
    ((uint2*)hi)[di] = uh; ((uint2*)lo)[di] = ul;
}

// ---------------- routing: parallel logits, then top-2 ----------------
__global__ void routing_kernel(const float* __restrict__ gate_w, float* __restrict__ aux_out) {
    __shared__ float logits[Bb][Ee];
    __shared__ float probs[Bb][Ee];
    int tid = threadIdx.x;                 // 512 threads
    {
        int pairBE = tid >> 3;
        int sub = tid & 7;
        int b = pairBE >> 3, e = pairBE & 7;
        const float* hv = g_h + (long)b * Ss * Hh;
        const float* w = gate_w + e * Hh;
        float acc = 0.f;
#pragma unroll 4
        for (int i = sub; i < Hh; i += 8) acc += hv[i] * w[i];
        acc += __shfl_xor_sync(0xffffffffu, acc, 1);
        acc += __shfl_xor_sync(0xffffffffu, acc, 2);
        acc += __shfl_xor_sync(0xffffffffu, acc, 4);
        if (sub == 0) logits[b][e] = acc;
    }
    __syncthreads();
    if (tid < Bb) {
        int b = tid;
        float mx = -1e30f;
        for (int e = 0; e < Ee; e++) mx = fmaxf(mx, logits[b][e]);
        float p[Ee]; float sum = 0.f;
        for (int e = 0; e < Ee; e++) { p[e] = expf(logits[b][e] - mx); sum += p[e]; }
        for (int e = 0; e < Ee; e++) { p[e] /= sum; probs[b][e] = p[e]; }
        int i1 = 0;
        for (int e = 1; e < Ee; e++) if (p[e] > p[i1]) i1 = e;
        int i2 = -1; float v2 = -1e30f;
        for (int e = 0; e < Ee; e++) if (e != i1 && p[e] > v2) { v2 = p[e]; i2 = e; }
        float denom = fmaxf(p[i1] + v2, 1e-8f);
        g_pair_e[2 * b]     = i1; g_pair_w[2 * b]     = p[i1] / denom;
        g_pair_e[2 * b + 1] = i2; g_pair_w[2 * b + 1] = v2 / denom;
    }
    __syncthreads();
    if (tid == 0) {
        float aux = 0.f;
        for (int e = 0; e < Ee; e++) {
            float imp = 0.f;
            for (int b = 0; b < Bb; b++) imp += probs[b][e];
            imp /= (float)Bb;
            int cnt = 0;
            for (int p = 0; p < NPAIR; p++) if (g_pair_e[p] == e) cnt++;
            float loadf = (float)cnt / (float)(Bb * 2);
            aux += (float)Ee * imp * loadf;
        }
        *aux_out = aux;
    }
}

// ---------------- persistent 4-tile mma GEMM, cross-tile pipelined, 3-term exact bf16 ----------------
// fuse: 0 = write C only; 1 = write C + hi/lo planes; 2 = silu(gate)*up -> planes (smem-staged)
#define STG   32768
#define T_AL  8192
#define T_WH  16384
#define T_WL  24576

__global__ void __launch_bounds__(256, 2) gemm_mma(
    const unsigned short* __restrict__ Ah, const unsigned short* __restrict__ Al, int aDiv,
    const unsigned short* __restrict__ Wh, const unsigned short* __restrict__ Wl,
    float* __restrict__ C, int K, int N,
    unsigned short* __restrict__ Ph, unsigned short* __restrict__ Pl, int fuse,
    int nT, int nTiles)
{
    extern __shared__ __align__(1024) char sm[];
    uint32_t sb = smem_u32(sm);

    int tid = threadIdx.x;
    int wid = tid >> 5, lane = tid & 31;
    int wm = wid & 1, wn = wid >> 1;

    int r_ = tid >> 2, c_ = tid & 3;
    uint32_t so[2]; long goK[2];
#pragma unroll
    for (int j = 0; j < 2; j++) {
        int row = r_ + 64 * j;
        so[j] = row * 64 + ((c_ ^ ((row >> 1) & 3)) << 4);
        goK[j] = (long)row * K + c_ * 8;
    }

    int l8 = lane & 7;
    int rowA = l8 + 8 * ((lane >> 3) & 1);
    int cA = lane >> 4;
    int rowB = l8 + 8 * (lane >> 4);
    int cB = (lane >> 3) & 1;
    int swA = (rowA >> 1) & 3, swB = (rowB >> 1) & 3;
    uint32_t aOff = (uint32_t)(wm * 64 + rowA) * 64;
    uint32_t bOff = (uint32_t)(wn * 32 + rowB) * 64;
    int g = lane >> 2, t2 = (lane & 3) * 2;
    int nc = K >> 5;

    // tile pointer decode
    auto tp = [&](int t, const unsigned short*& a_h, const unsigned short*& a_l,
                  const unsigned short*& w_h, const unsigned short*& w_l,
                  int& pr, int& mm0, int& nn0) {
        int m_ = t & 3;
        int rest = t >> 2;
        int n_ = rest % nT;
        pr = rest / nT;
        mm0 = m_ * 128; nn0 = n_ * 128;
        long aO = (long)(pr / aDiv) * Ss * K + (long)mm0 * K;
        long wO = (long)g_pair_e[pr] * N * K + (long)nn0 * K;
        a_h = Ah + aO; a_l = Al + aO;
        w_h = Wh + wO; w_l = Wl + wO;
    };

    int t = blockIdx.x;
    const unsigned short *pAh, *pAl, *pWh, *pWl;
    int pair, m0, n0;
    tp(t, pAh, pAl, pWh, pWl, pair, m0, n0);

    // prologue: chunks 0,1 of first tile
#pragma unroll
    for (int s = 0; s < 2; s++) {
        uint32_t st = sb + s * STG;
        long kb = (long)s * 32;
#pragma unroll
        for (int j = 0; j < 2; j++) {
            CP_ASYNC(st + so[j],        pAh + goK[j] + kb);
            CP_ASYNC(st + T_AL + so[j], pAl + goK[j] + kb);
            CP_ASYNC(st + T_WH + so[j], pWh + goK[j] + kb);
            CP_ASYNC(st + T_WL + so[j], pWl + goK[j] + kb);
        }
        CP_COMMIT();
    }
    int sIdx = 0;

    while (true) {
        float acc[4][4][4];
#pragma unroll
        for (int i = 0; i < 4; i++)
#pragma unroll
            for (int j = 0; j < 4; j++)
#pragma unroll
                for (int k = 0; k < 4; k++) acc[i][j][k] = 0.f;

        for (int c = 0; c < nc; c++) {
            CP_WAIT1();
            __syncthreads();
            int pf = c + 2;
            if (pf < nc) {
                int s2 = sIdx + 2; if (s2 >= 3) s2 -= 3;
                uint32_t st = sb + s2 * STG;
                long kb = (long)pf * 32;
#pragma unroll
                for (int j = 0; j < 2; j++) {
                    CP_ASYNC(st + so[j],        pAh + goK[j] + kb);
                    CP_ASYNC(st + T_AL + so[j], pAl + goK[j] + kb);
                    CP_ASYNC(st + T_WH + so[j], pWh + goK[j] + kb);
                    CP_ASYNC(st + T_WL + so[j], pWl + goK[j] + kb);
                }
            } else {
                int tn = t + gridDim.x;
                if (tn < nTiles) {
                    // cross-tile prefetch: chunks 0/1 of this CTA's next tile
                    const unsigned short *nAh, *nAl, *nWh, *nWl;
                    int npr, nm, nn;
                    tp(tn, nAh, nAl, nWh, nWl, npr, nm, nn);
                    int s2 = sIdx + 2; if (s2 >= 3) s2 -= 3;
                    uint32_t st = sb + s2 * STG;
                    long kb = (long)(pf - nc) * 32;
#pragma unroll
                    for (int j = 0; j < 2; j++) {
                        CP_ASYNC(st + so[j],        nAh + goK[j] + kb);
                        CP_ASYNC(st + T_AL + so[j], nAl + goK[j] + kb);
                        CP_ASYNC(st + T_WH + so[j], nWh + goK[j] + kb);
                        CP_ASYNC(st + T_WL + so[j], nWl + goK[j] + kb);
                    }
                }
            }
            CP_COMMIT();

            uint32_t st = sb + sIdx * STG;
#pragma unroll
            for (int kk = 0; kk < 2; kk++) {
                uint32_t kxA = (uint32_t)(((2 * kk + cA) ^ swA) << 4);
                uint32_t kxB = (uint32_t)(((2 * kk + cB) ^ swB) << 4);
                unsigned af[4][4], bh[4][2], bl[4][2];
#pragma unroll
                for (int mt = 0; mt < 4; mt++)
                    LDMX4(af[mt][0], af[mt][1], af[mt][2], af[mt][3], st + aOff + mt * 1024 + kxA);
                LDMX4(bh[0][0], bh[0][1], bh[1][0], bh[1][1], st + T_WH + bOff + kxB);
                LDMX4(bh[2][0], bh[2][1], bh[3][0], bh[3][1], st + T_WH + bOff + 1024 + kxB);
#pragma unroll
                for (int mt = 0; mt < 4; mt++) {
#pragma unroll
                    for (int nt = 0; nt < 4; nt++)
                        MMA16816(acc[mt][nt], af[mt][0], af[mt][1], af[mt][2], af[mt][3], bh[nt][0], bh[nt][1]);
                    if (mt == 0) { LDMX4(bl[0][0], bl[0][1], bl[1][0], bl[1][1], st + T_WL + bOff + kxB); }
                    if (mt == 1) { LDMX4(bl[2][0], bl[2][1], bl[3][0], bl[3][1], st + T_WL + bOff + 1024 + kxB); }
                }
#pragma unroll
                for (int mt = 0; mt < 4; mt++) {
#pragma unroll
                    for (int nt = 0; nt < 4; nt++)
                        MMA16816(acc[mt][nt], af[mt][0], af[mt][1], af[mt][2], af[mt][3], bl[nt][0], bl[nt][1]);
                    LDMX4(af[mt][0], af[mt][1], af[mt][2], af[mt][3], st + T_AL + aOff + mt * 1024 + kxA);
                }
#pragma unroll
                for (int mt = 0; mt < 4; mt++)
#pragma unroll
                    for (int nt = 0; nt < 4; nt++)
                        MMA16816(acc[mt][nt], af[mt][0], af[mt][1], af[mt][2], af[mt][3], bh[nt][0], bh[nt][1]);
            }
            sIdx++; if (sIdx >= 3) sIdx -= 3;
        }

        // ---- epilogue ----
        if (fuse == 2) {
            // free stage = the one chunk nc-1 just consumed = (sIdx+2)%3
            int fs = sIdx + 2; if (fs >= 3) fs -= 3;
            unsigned short* sh = (unsigned short*)(sm + fs * STG);
            unsigned short* sl = (unsigned short*)(sm + fs * STG + 16384);
            __syncthreads();   // all warps done reading stage fs
#pragma unroll
            for (int mt = 0; mt < 4; mt++) {
                int ml = wm * 64 + mt * 16 + g;
#pragma unroll
                for (int nt = 0; nt < 4; nt++) {
                    int jl = (wn * 32 + nt * 8 + t2) >> 1;
                    float g0 = acc[mt][nt][0], u0 = acc[mt][nt][1];
                    float g1 = acc[mt][nt][2], u1 = acc[mt][nt][3];
                    float y0 = g0 / (1.f + expf(-g0)) * u0;
                    float y1 = g1 / (1.f + expf(-g1)) * u1;
                    unsigned short h, l;
                    split2(y0, h, l); sh[ml * 64 + jl] = h; sl[ml * 64 + jl] = l;
                    split2(y1, h, l); sh[(ml + 8) * 64 + jl] = h; sl[(ml + 8) * 64 + jl] = l;
                }
            }
            __syncthreads();
            int row = tid >> 1, half = tid & 1;
            int NH = N >> 1;   // = INTER
            long gbase = ((long)pair * Ss + m0 + row) * NH + (n0 >> 1) + half * 32;
            const uint4* s4h = (const uint4*)(sh + row * 64 + half * 32);
            const uint4* s4l = (const uint4*)(sl + row * 64 + half * 32);
#pragma unroll
            for (int q = 0; q < 4; q++) {
                *(uint4*)(Ph + gbase + q * 8) = s4h[q];
                *(uint4*)(Pl + gbase + q * 8) = s4l[q];
            }
        } else {
            float* Cp = C + (long)pair * Ss * N;
#pragma unroll
            for (int mt = 0; mt < 4; mt++) {
                int m = m0 + wm * 64 + mt * 16 + g;
#pragma unroll
                for (int nt = 0; nt < 4; nt++) {
                    int n = n0 + wn * 32 + nt * 8 + t2;
                    *(float2*)(Cp + (long)m * N + n)       = make_float2(acc[mt][nt][0], acc[mt][nt][1]);
                    *(float2*)(Cp + (long)(m + 8) * N + n) = make_float2(acc[mt][nt][2], acc[mt][nt][3]);
                    if (fuse == 1) {
                        long r0 = ((long)pair * Ss + m) * N + n;
                        long r1 = ((long)pair * Ss + m + 8) * N + n;
                        unsigned short h0, l0, h1, l1;
                        split2(acc[mt][nt][0], h0, l0); split2(acc[mt][nt][1], h1, l1);
                        *(unsigned*)(Ph + r0) = (unsigned)h0 | ((unsigned)h1 << 16);
                        *(unsigned*)(Pl + r0) = (unsigned)l0 | ((unsigned)l1 << 16);
                        split2(acc[mt][nt][2], h0, l0); split2(acc[mt][nt][3], h1, l1);
                        *(unsigned*)(Ph + r1) = (unsigned)h0 | ((unsigned)h1 << 16);
                        *(unsigned*)(Pl + r1) = (unsigned)l0 | ((unsigned)l1 << 16);
                    }
                }
            }
        }

        t += gridDim.x;
        if (t >= nTiles) break;
        tp(t, pAh, pAl, pWh, pWl, pair, m0, n0);
    }
}

// ---------------- prep attention: rope + scale + hi/lo split + V transpose ----------------
__global__ void prep_attn(const float* __restrict__ cosb, const float* __restrict__ sinb) {
    int s = blockIdx.x, pair = blockIdx.y;
    int tid = threadIdx.x;
    int hh = tid >> 5, d = tid & 31;
    const float* base = g_qkv + ((long)pair * Ss + s) * QKVW;
    long ph = (long)pair * 8 + hh;
    float c1 = cosb[s * HD + d],      s1 = sinb[s * HD + d];
    float c2 = cosb[s * HD + d + 32], s2 = sinb[s * HD + d + 32];
    {
        float x1 = base[hh * HD + d], x2 = base[hh * HD + d + 32];
        float y1 = (x1 * c1 - x2 * s1) * 0.125f;
        float y2 = (x2 * c2 + x1 * s2) * 0.125f;
        long o = (ph * Ss + s) * HD + d;
        unsigned short h0, l0, h1, l1;
        split2(y1, h0, l0); split2(y2, h1, l1);
        g_aw[WQH + o] = h0; g_aw[WQL + o] = l0;
        g_aw[WQH + o + 32] = h1; g_aw[WQL + o + 32] = l1;
    }
    {
        float x1 = base[512 + hh * HD + d], x2 = base[512 + hh * HD + d + 32];
        float y1 = x1 * c1 - x2 * s1;
        float y2 = x2 * c2 + x1 * s2;
        long o = (ph * Ss + s) * HD + d;
        unsigned short h0, l0, h1, l1;
        split2(y1, h0, l0); split2(y2, h1, l1);
        g_aw[WKH + o] = h0; g_aw[WKL + o] = l0;
        g_aw[WKH + o + 32] = h1; g_aw[WKL + o + 32] = l1;
    }
    {
        float v1 = base[1024 + hh * HD + d], v2 = base[1024 + hh * HD + d + 32];
        long o1 = (ph * HD + d) * Ss + s;
        long o2 = (ph * HD + d + 32) * Ss + s;
        unsigned short h0, l0, h1, l1;
        split2(v1, h0, l0); split2(v2, h1, l1);
        g_aw[WVH + o1] = h0; g_aw[WVL + o1] = l0;
        g_aw[WVH + o2] = h1; g_aw[WVL + o2] = l1;
    }
}

// ---------------- mma flash attention ----------------
#define ASMEM 98304

__global__ void __launch_bounds__(256) attn_mma(unsigned short* __restrict__ Ph,
                                                unsigned short* __restrict__ Pl) {
    extern __shared__ __align__(1024) char sm2[];
    uint32_t sb = smem_u32(sm2);
    int tid = threadIdx.x, w = tid >> 5, lane = tid & 31;
    int qt = blockIdx.x, head = blockIdx.y, pair = blockIdx.z;
    int q0 = qt * 128;
    long ph = (long)pair * 8 + head;
    const unsigned short* Qh = g_aw + WQH + ph * Ss * HD;
    const unsigned short* Ql = g_aw + WQL + ph * Ss * HD;
    const unsigned short* Kh = g_aw + WKH + ph * Ss * HD;
    const unsigned short* Kl = g_aw + WKL + ph * Ss * HD;
    const unsigned short* Vh = g_aw + WVH + ph * HD * Ss;
    const unsigned short* Vl = g_aw + WVL + ph * HD * Ss;

    int ldRow = tid >> 3, ldC = tid & 7;

#pragma unroll
    for (int j = 0; j < 4; j++) {
        int row = ldRow + 32 * j;
        uint32_t so = row * 128 + ((ldC ^ (row & 7)) << 4);
        CP_ASYNC(sb + so,         Qh + (long)(q0 + row) * HD + ldC * 8);
        CP_ASYNC(sb + 16384 + so, Ql + (long)(q0 + row) * HD + ldC * 8);
    }
    auto issue = [&](int buf, int kt) {
        uint32_t st = sb + 32768 + buf * 32768;
#pragma unroll
        for (int j = 0; j < 2; j++) {
            int row = ldRow + 32 * j;
            uint32_t so = row * 128 + ((ldC ^ (row & 7)) << 4);
            long kOff = (long)(kt * 64 + row) * HD + ldC * 8;
            CP_ASYNC(st + so,         Kh + kOff);
            CP_ASYNC(st + 8192 + so,  Kl + kOff);
            long vOff = (long)row * Ss + kt * 64 + ldC * 8;
            CP_ASYNC(st + 16384 + so, Vh + vOff);
            CP_ASYNC(st + 24576 + so, Vl + vOff);
        }
    };
    issue(0, 0); CP_COMMIT();
    issue(1, 1); CP_COMMIT();

    int l8 = lane & 7;
    int rowA = l8 + 8 * ((lane >> 3) & 1);
    int cA = lane >> 4;
    int rowB = l8 + 8 * (lane >> 4);
    int cB = (lane >> 3) & 1;
    uint32_t aOff = (uint32_t)(w * 16 + rowA) * 128;
    uint32_t bOff = (uint32_t)rowB * 128;

    float o[8][4];
#pragma unroll
    for (int f = 0; f < 8; f++)
#pragma unroll
        for (int k = 0; k < 4; k++) o[f][k] = 0.f;
    float mr[2] = {-1e30f, -1e30f}, lr[2] = {0.f, 0.f};

    for (int kt = 0; kt < 8; kt++) {
        CP_WAIT1();
        __syncthreads();
        int buf = kt & 1;
        uint32_t st = sb + 32768 + buf * 32768;

        float sc[8][4];
#pragma unroll
        for (int f = 0; f < 8; f++)
#pragma unroll
            for (int k = 0; k < 4; k++) sc[f][k] = 0.f;
#pragma unroll
        for (int pass = 0; pass < 3; pass++) {
            uint32_t aB = sb + (pass == 1 ? 16384u : 0u) + aOff;
            uint32_t bB = st + (pass == 2 ? 8192u : 0u) + bOff;
#pragma unroll
            for (int kk = 0; kk < 4; kk++) {
                unsigned af[4], bfr[8][2];
                uint32_t kxA = (uint32_t)(((2 * kk + cA) ^ l8) << 4);
                uint32_t kxB = (uint32_t)(((2 * kk + cB) ^ l8) << 4);
                LDMX4(af[0], af[1], af[2], af[3], aB + kxA);
#pragma unroll
                for (int n2 = 0; n2 < 4; n2++)
                    LDMX4(bfr[2*n2][0], bfr[2*n2][1], bfr[2*n2+1][0], bfr[2*n2+1][1],
                          bB + n2 * 2048 + kxB);
#pragma unroll
                for (int nt = 0; nt < 8; nt++)
                    MMA16816(sc[nt], af[0], af[1], af[2], af[3], bfr[nt][0], bfr[nt][1]);
            }
        }

#pragma unroll
        for (int r = 0; r < 2; r++) {
            float mx = -1e30f;
#pragma unroll
            for (int f = 0; f < 8; f++) mx = fmaxf(mx, fmaxf(sc[f][2*r], sc[f][2*r+1]));
            mx = fmaxf(mx, __shfl_xor_sync(0xffffffffu, mx, 1));
            mx = fmaxf(mx, __shfl_xor_sync(0xffffffffu, mx, 2));
            float mn = fmaxf(mr[r], mx);
            float scale = expf(mr[r] - mn);
            mr[r] = mn;
            float ls = 0.f;
#pragma unroll
            for (int f = 0; f < 8; f++) {
                float p0 = expf(sc[f][2*r] - mn);
                float p1 = expf(sc[f][2*r+1] - mn);
                sc[f][2*r] = p0; sc[f][2*r+1] = p1;
                ls += p0 + p1;
            }
            ls += __shfl_xor_sync(0xffffffffu, ls, 1);
            ls += __shfl_xor_sync(0xffffffffu, ls, 2);
            lr[r] = lr[r] * scale + ls;
#pragma unroll
            for (int f = 0; f < 8; f++) { o[f][2*r] *= scale; o[f][2*r+1] *= scale; }
        }

        unsigned aPh[4][4], aPl[4][4];
#pragma unroll
        for (int j = 0; j < 4; j++) {
#pragma unroll
            for (int u = 0; u < 4; u++) {
                int f = 2 * j + (u >> 1);
                int c = (u & 1) * 2;
                unsigned short h0, l0, h1, l1;
                split2(sc[f][c], h0, l0);
                split2(sc[f][c + 1], h1, l1);
                aPh[j][u] = (unsigned)h0 | ((unsigned)h1 << 16);
                aPl[j][u] = (unsigned)l0 | ((unsigned)l1 << 16);
            }
        }

#pragma unroll
        for (int pass = 0; pass < 3; pass++) {
            uint32_t vB = st + (pass == 2 ? 24576u : 16384u) + bOff;
#pragma unroll
            for (int j = 0; j < 4; j++) {
                unsigned bfr[8][2];
                uint32_t kxB = (uint32_t)(((2 * j + cB) ^ l8) << 4);
#pragma unroll
                for (int n2 = 0; n2 < 4; n2++)
                    LDMX4(bfr[2*n2][0], bfr[2*n2][1], bfr[2*n2+1][0], bfr[2*n2+1][1],
                          vB + n2 * 2048 + kxB);
                const unsigned (*aP)[4] = (pass == 1) ? aPl : aPh;
#pragma unroll
                for (int nt = 0; nt < 8; nt++)
                    MMA16816(o[nt], aP[j][0], aP[j][1], aP[j][2], aP[j][3],
                             bfr[nt][0], bfr[nt][1]);
            }
        }
        __syncthreads();
        if (kt + 2 < 8) issue(buf, kt + 2);
        CP_COMMIT();
    }

    int g = lane >> 2, t2 = (lane & 3) * 2;
#pragma unroll
    for (int r = 0; r < 2; r++) {
        float inv = 1.f / lr[r];
        long row = (long)pair * Ss + q0 + w * 16 + g + 8 * r;
#pragma unroll
        for (int nt = 0; nt < 8; nt++) {
            float y0 = o[nt][2*r] * inv, y1 = o[nt][2*r+1] * inv;
            unsigned short h0, l0, h1, l1;
            split2(y0, h0, l0); split2(y1, h1, l1);
            long off = row * HSUB + head * HD + nt * 8 + t2;
            *(unsigned*)(Ph + off) = (unsigned)h0 | ((unsigned)h1 << 16);
            *(unsigned*)(Pl + off) = (unsigned)l0 | ((unsigned)l1 << 16);
        }
    }
}

// ---------------- residual + rmsnorm, fused hi/lo split ----------------
__global__ void resnorm2_kernel(unsigned short* __restrict__ Ph, unsigned short* __restrict__ Pl) {
    long row = blockIdx.x;
    float* a = g_hs + row * HSUB;
    const float* t = g_tmp + row * HSUB;
    int tid = threadIdx.x;
    float v0 = a[tid] + t[tid];
    float v1 = a[tid + 256] + t[tid + 256];
    float ss = v0 * v0 + v1 * v1;
#pragma unroll
    for (int off = 16; off; off >>= 1) ss += __shfl_xor_sync(0xffffffffu, ss, off);
    __shared__ float red[8];
    __shared__ float stot;
    if ((tid & 31) == 0) red[tid >> 5] = ss;
    __syncthreads();
    if (tid == 0) {
        float tsum = 0.f;
        for (int i = 0; i < 8; i++) tsum += red[i];
        stot = tsum;
    }
    __syncthreads();
    float scale = rsqrtf(stot * (1.f / HSUB) + 1e-5f);
    float y0 = v0 * scale, y1 = v1 * scale;
    a[tid] = y0; a[tid + 256] = y1;
    unsigned short h, l;
    split2(y0, h, l); Ph[row * HSUB + tid] = h; Pl[row * HSUB + tid] = l;
    split2(y1, h, l); Ph[row * HSUB + tid + 256] = h; Pl[row * HSUB + tid + 256] = l;
}

// ---------------- final ----------------
__global__ void final_kernel(float* __restrict__ out) {
    int b = blockIdx.y, s = blockIdx.x;
    float w0 = g_pair_w[2 * b], w1 = g_pair_w[2 * b + 1];
    long r = (long)b * Ss + s;
    const float* hp = g_h + r * Hh;
    const float* u0 = g_up + ((long)(2 * b) * Ss + s) * Hh;
    const float* u1 = g_up + ((long)(2 * b + 1) * Ss + s) * Hh;
    int tid = threadIdx.x;
    int c = tid * 4;
    float4 vh = *(const float4*)(hp + c);
    float4 v0 = *(const float4*)(u0 + c);
    float4 v1 = *(const float4*)(u1 + c);
    float y[4];
    y[0] = vh.x + w0 * v0.x + w1 * v1.x;
    y[1] = vh.y + w0 * v0.y + w1 * v1.y;
    y[2] = vh.z + w0 * v0.z + w1 * v1.z;
    y[3] = vh.w + w0 * v0.w + w1 * v1.w;
    float ss = y[0] * y[0] + y[1] * y[1] + y[2] * y[2] + y[3] * y[3];
#pragma unroll
    for (int off = 16; off; off >>= 1) ss += __shfl_xor_sync(0xffffffffu, ss, off);
    __shared__ float red[8];
    __shared__ float stot;
    if ((tid & 31) == 0) red[tid >> 5] = ss;
    __syncthreads();
    if (tid == 0) {
        float tsum = 0.f;
        for (int i = 0; i < 8; i++) tsum += red[i];
        stot = tsum;
    }
    __syncthreads();
    float scale = rsqrtf(stot * (1.f / Hh) + 1e-5f);
    float4 o;
    o.x = y[0] * scale; o.y = y[1] * scale; o.z = y[2] * scale; o.w = y[3] * scale;
    *(float4*)(out + r * Hh + c) = o;
}

// ---------------- launch ----------------
extern "C" void kernel_launch(void* const* d_in, const int* in_sizes, int n_in,
                              void* d_out, int out_size) {
    const float* hidden     = (const float*)d_in[0];
    const float* inj        = (const float*)d_in[1];
    const float* cosb       = (const float*)d_in[2];
    const float* sinb       = (const float*)d_in[3];
    const float* gate_w     = (const float*)d_in[4];
    const float* down_w     = (const float*)d_in[5];
    const float* up_w       = (const float*)d_in[6];
    const float* qkv_w      = (const float*)d_in[7];
    const float* o_w        = (const float*)d_in[8];
    const float* gate_up_w  = (const float*)d_in[9];
    const float* mlp_down_w = (const float*)d_in[10];
    float* out = (float*)d_out;

    void* vp;
    cudaGetSymbolAddress(&vp, g_hs);  float* p_hs  = (float*)vp;
    cudaGetSymbolAddress(&vp, g_qkv); float* p_qkv = (float*)vp;
    cudaGetSymbolAddress(&vp, g_tmp); float* p_tmp = (float*)vp;
    cudaGetSymbolAddress(&vp, g_up);  float* p_up  = (float*)vp;
    cudaGetSymbolAddress(&vp, g_wh);  unsigned short* p_wh = (unsigned short*)vp;
    cudaGetSymbolAddress(&vp, g_wl);  unsigned short* p_wl = (unsigned short*)vp;
    cudaGetSymbolAddress(&vp, g_p0h); unsigned short* p0h = (unsigned short*)vp;
    cudaGetSymbolAddress(&vp, g_p0l); unsigned short* p0l = (unsigned short*)vp;
    cudaGetSymbolAddress(&vp, g_p1h); unsigned short* p1h = (unsigned short*)vp;
    cudaGetSymbolAddress(&vp, g_p1l); unsigned short* p1l = (unsigned short*)vp;

    cudaFuncSetAttribute(gemm_mma, cudaFuncAttributeMaxDynamicSharedMemorySize, 3 * STG);
    cudaFuncSetAttribute(attn_mma, cudaFuncAttributeMaxDynamicSharedMemorySize, ASMEM);

    int nsm = 148;
    cudaDeviceGetAttribute(&nsm, cudaDevAttrMultiProcessorCount, 0);
    int cap = 2 * nsm;
    auto grid_for = [&](int nTiles) { return nTiles < cap ? nTiles : cap; };

    // all weights -> planes, one launch (gate_up rows interleaved)
    cvtw_kernel<<<34816, 256>>>(down_w, qkv_w, o_w, gate_up_w, mlp_down_w, up_w, p_wh, p_wl);

    // 1. h = hidden + injection (fused split into P0) ; routing
    add3_kernel<<<(Bb * Ss * Hh / 4) / 256, 256>>>(hidden, inj, p0h, p0l);
    routing_kernel<<<1, 512>>>(gate_w, out + (out_size - 1));

    // 2. hs0 = h @ down_w^T  (K=1024, N=512); planes -> P1
    {
        int nT = HSUB / 128, nTiles = 4 * nT * NPAIR;
        gemm_mma<<<grid_for(nTiles), 256, 3 * STG>>>(
            p0h, p0l, 2, p_wh + OFF_DOWN, p_wl + OFF_DOWN, p_hs, Hh, HSUB, p1h, p1l, 1, nT, nTiles);
    }
    // 3. qkv = hs0 @ qkv_w^T  (K=512, N=1536)
    {
        int nT = QKVW / 128, nTiles = 4 * nT * NPAIR;
        gemm_mma<<<grid_for(nTiles), 256, 3 * STG>>>(
            p1h, p1l, 1, p_wh + OFF_QKV, p_wl + OFF_QKV, p_qkv, HSUB, QKVW,
            (unsigned short*)0, (unsigned short*)0, 0, nT, nTiles);
    }
    // 4. prep + attention (planes -> P0)
    prep_attn<<<dim3(Ss, NPAIR), 256>>>(cosb, sinb);
    attn_mma<<<dim3(4, NHEAD, NPAIR), 256, ASMEM>>>(p0h, p0l);

    // 5. tmp = att @ o_w^T  (K=512, N=512)
    {
        int nT = HSUB / 128, nTiles = 4 * nT * NPAIR;
        gemm_mma<<<grid_for(nTiles), 256, 3 * STG>>>(
            p0h, p0l, 1, p_wh + OFF_O, p_wl + OFF_O, p_tmp, HSUB, HSUB,
            (unsigned short*)0, (unsigned short*)0, 0, nT, nTiles);
    }
    // 6. hs1 = rmsnorm(hs0 + tmp) -> planes P1
    resnorm2_kernel<<<NPAIR * Ss, 256>>>(p1h, p1l);

    // 7+8. act = silu(gate)*up fused into gu GEMM epilogue (smem-staged) -> planes P0
    {
        int nT = GUW / 128, nTiles = 4 * nT * NPAIR;
        gemm_mma<<<grid_for(nTiles), 256, 3 * STG>>>(
            p1h, p1l, 1, p_wh + OFF_GU, p_wl + OFF_GU, (float*)0, HSUB, GUW, p0h, p0l, 2, nT, nTiles);
    }
    // 9. tmp = act @ mlp_down_w^T  (K=1536, N=512)
    {
        int nT = HSUB / 128, nTiles = 4 * nT * NPAIR;
        gemm_mma<<<grid_for(nTiles), 256, 3 * STG>>>(
            p0h, p0l, 1, p_wh + OFF_MLPD, p_wl + OFF_MLPD, p_tmp, INTER, HSUB,
            (unsigned short*)0, (unsigned short*)0, 0, nT, nTiles);
    }
    // 10. hs2 = rmsnorm(hs1 + tmp) -> planes P1
    resnorm2_kernel<<<NPAIR * Ss, 256>>>(p1h, p1l);

    // 11. up_out = hs2 @ up_w^T  (K=512, N=1024)
    {
        int nT = Hh / 128, nTiles = 4 * nT * NPAIR;
        gemm_mma<<<grid_for(nTiles), 256, 3 * STG>>>(
            p1h, p1l, 1, p_wh + OFF_UP, p_wl + OFF_UP, p_up, HSUB, Hh,
            (unsigned short*)0, (unsigned short*)0, 0, nT, nTiles);
    }
    // 12. out = rmsnorm(h + w0*u0 + w1*u1)
    final_kernel<<<dim3(Ss, Bb), 256>>>(out);
}

// round 16
// speedup vs baseline: 1.0240x; 1.0240x over previous
#include <cuda_runtime.h>
#include <cuda_bf16.h>
#include <math.h>
#include <stdint.h>

#define Bb 8
#define Ss 512
#define Hh 1024
#define Ee 8
#define NHEAD 8
#define HD 64
#define HSUB 512
#define INTER 1536
#define NPAIR 16
#define QKVW 1536
#define GUW 3072

// ---------------- scratch ----------------
__device__ float g_h[Bb * Ss * Hh];
__device__ float g_hs[NPAIR * Ss * HSUB];
__device__ float g_qkv[NPAIR * Ss * QKVW];
__device__ float g_tmp[NPAIR * Ss * HSUB];
__device__ float g_up[NPAIR * Ss * Hh];
__device__ int   g_pair_e[NPAIR];
__device__ float g_pair_w[NPAIR];

#define OFF_DOWN 0L
#define OFF_QKV  4194304L
#define OFF_O    10485760L
#define OFF_GU   12582912L
#define OFF_MLPD 25165824L
#define OFF_UP   31457280L
#define W_TOTAL  35651584L
__device__ unsigned short g_wh[W_TOTAL];
__device__ unsigned short g_wl[W_TOTAL];
__device__ unsigned short g_p0h[NPAIR * Ss * INTER];
__device__ unsigned short g_p0l[NPAIR * Ss * INTER];
__device__ unsigned short g_p1h[NPAIR * Ss * INTER];
__device__ unsigned short g_p1l[NPAIR * Ss * INTER];
#define AWP 4194304L
__device__ unsigned short g_aw[6 * AWP];
#define WQH 0L
#define WQL (1*AWP)
#define WKH (2*AWP)
#define WKL (3*AWP)
#define WVH (4*AWP)
#define WVL (5*AWP)

// ---------------- PTX helpers ----------------
__device__ __forceinline__ uint32_t smem_u32(const void* p) {
    uint32_t a;
    asm("{ .reg .u64 t; cvta.to.shared.u64 t, %1; cvt.u32.u64 %0, t; }" : "=r"(a) : "l"(p));
    return a;
}
#define CP_ASYNC(sm, gp) asm volatile("cp.async.cg.shared.global [%0], [%1], 16;" :: "r"(sm), "l"(gp))
#define CP_COMMIT()      asm volatile("cp.async.commit_group;" ::: "memory")
#define CP_WAIT1()       asm volatile("cp.async.wait_group 1;" ::: "memory")
#define LDMX4(r0, r1, r2, r3, a) \
    asm volatile("ldmatrix.sync.aligned.m8n8.x4.shared.b16 {%0,%1,%2,%3}, [%4];" \
        : "=r"(r0), "=r"(r1), "=r"(r2), "=r"(r3) : "r"(a))
#define MMA16816(d, a0, a1, a2, a3, b0, b1) \
    asm volatile("mma.sync.aligned.m16n8k16.row.col.f32.bf16.bf16.f32 " \
        "{%0,%1,%2,%3}, {%4,%5,%6,%7}, {%8,%9}, {%0,%1,%2,%3};" \
        : "+f"((d)[0]), "+f"((d)[1]), "+f"((d)[2]), "+f"((d)[3]) \
        : "r"(a0), "r"(a1), "r"(a2), "r"(a3), "r"(b0), "r"(b1))

__device__ __forceinline__ void split2(float x, unsigned short& h, unsigned short& l) {
    __nv_bfloat16 hb = __float2bfloat16(x);
    h = __bfloat16_as_ushort(hb);
    l = __bfloat16_as_ushort(__float2bfloat16(x - __bfloat162float(hb)));
}

// ---------------- h = hidden + injection, fused hi/lo split ----------------
__global__ void add3_kernel(const float* __restrict__ a, const float* __restrict__ b,
                            unsigned short* __restrict__ hi, unsigned short* __restrict__ lo) {
    long i = (long)blockIdx.x * 256 + threadIdx.x;
    float4 va = ((const float4*)a)[i];
    float4 vb = ((const float4*)b)[i];
    float x[4] = {va.x + vb.x, va.y + vb.y, va.z + vb.z, va.w + vb.w};
    ((float4*)g_h)[i] = make_float4(x[0], x[1], x[2], x[3]);
    unsigned int h[4], l[4];
#pragma unroll
    for (int j = 0; j < 4; j++) { unsigned short hs_, ls_; split2(x[j], hs_, ls_); h[j] = hs_; l[j] = ls_; }
    uint2 uh, ul;
    uh.x = h[0] | (h[1] << 16); uh.y = h[2] | (h[3] << 16);
    ul.x = l[0] | (l[1] << 16); ul.y = l[2] | (l[3] << 16);
    ((uint2*)hi)[i] = uh; ((uint2*)lo)[i] = ul;
}

// ---------------- all weights -> 2 bf16 planes; gate_up rows interleaved ----------------
__global__ void cvtw_kernel(const float* __restrict__ p0, const float* __restrict__ p1,
                            const float* __restrict__ p2, const float* __restrict__ p3,
                            const float* __restrict__ p4, const float* __restrict__ p5,
                            unsigned short* __restrict__ hi, unsigned short* __restrict__ lo) {
    long i = (long)blockIdx.x * 256 + threadIdx.x;   // float4 index, total 8912896
    const float* src; long off;
    if (i < 1048576L)      { src = p0; off = 0L; }
    else if (i < 2621440L) { src = p1; off = 1048576L; }
    else if (i < 3145728L) { src = p2; off = 2621440L; }
    else if (i < 6291456L) { src = p3; off = 3145728L; }
    else if (i < 7864320L) { src = p4; off = 6291456L; }
    else                   { src = p5; off = 7864320L; }
    float4 v = ((const float4*)src)[i - off];
    float x[4] = {v.x, v.y, v.z, v.w};
    unsigned int h[4], l[4];
#pragma unroll
    for (int j = 0; j < 4; j++) { unsigned short hs_, ls_; split2(x[j], hs_, ls_); h[j] = hs_; l[j] = ls_; }
    uint2 uh, ul;
    uh.x = h[0] | (h[1] << 16); uh.y = h[2] | (h[3] << 16);
    ul.x = l[0] | (l[1] << 16); ul.y = l[2] | (l[3] << 16);
    long di = i;
    if (i >= 3145728L && i < 6291456L) {
        long idx4 = i - 3145728L;
        long exp_ = idx4 / 393216L;          // per-expert: 3072*512/4 float4
        long rem = idx4 - exp_ * 393216L;
        long row = rem >> 7;                  // 128 float4 per 512-col row
        long col4 = rem & 127;
        long nrow = (row < 1536) ? 2 * row : 2 * (row - 1536) + 1;
        di = 3145728L + exp_ * 393216L + nrow * 128 + col4;
    }
    ((uint2*)hi)[di] = uh; ((uint2*)lo)[di] = ul;
}

// ---------------- routing: parallel logits, then top-2 ----------------
__global__ void routing_kernel(const float* __restrict__ gate_w, float* __restrict__ aux_out) {
    __shared__ float logits[Bb][Ee];
    __shared__ float probs[Bb][Ee];
    int tid = threadIdx.x;                 // 512 threads
    {
        int pairBE = tid >> 3;
        int sub = tid & 7;
        int b = pairBE >> 3, e = pairBE & 7;
        const float* hv = g_h + (long)b * Ss * Hh;
        const float* w = gate_w + e * Hh;
        float acc = 0.f;
#pragma unroll 4
        for (int i = sub; i < Hh; i += 8) acc += hv[i] * w[i];
        acc += __shfl_xor_sync(0xffffffffu, acc, 1);
        acc += __shfl_xor_sync(0xffffffffu, acc, 2);
        acc += __shfl_xor_sync(0xffffffffu, acc, 4);
        if (sub == 0) logits[b][e] = acc;
    }
    __syncthreads();
    if (tid < Bb) {
        int b = tid;
        float mx = -1e30f;
        for (int e = 0; e < Ee; e++) mx = fmaxf(mx, logits[b][e]);
        float p[Ee]; float sum = 0.f;
        for (int e = 0; e < Ee; e++) { p[e] = expf(logits[b][e] - mx); sum += p[e]; }
        for (int e = 0; e < Ee; e++) { p[e] /= sum; probs[b][e] = p[e]; }
        int i1 = 0;
        for (int e = 1; e < Ee; e++) if (p[e] > p[i1]) i1 = e;
        int i2 = -1; float v2 = -1e30f;
        for (int e = 0; e < Ee; e++) if (e != i1 && p[e] > v2) { v2 = p[e]; i2 = e; }
        float denom = fmaxf(p[i1] + v2, 1e-8f);
        g_pair_e[2 * b]     = i1; g_pair_w[2 * b]     = p[i1] / denom;
        g_pair_e[2 * b + 1] = i2; g_pair_w[2 * b + 1] = v2 / denom;
    }
    __syncthreads();
    if (tid == 0) {
        float aux = 0.f;
        for (int e = 0; e < Ee; e++) {
            float imp = 0.f;
            for (int b = 0; b < Bb; b++) imp += probs[b][e];
            imp /= (float)Bb;
            int cnt = 0;
            for (int p = 0; p < NPAIR; p++) if (g_pair_e[p] == e) cnt++;
            float loadf = (float)cnt / (float)(Bb * 2);
            aux += (float)Ee * imp * loadf;
        }
        *aux_out = aux;
    }
}

// ---------------- 4-tile mma GEMM, 3-term exact bf16, BK=32, 3-stage, pipelined ----------------
// fuse: 0 = write C only; 1 = write C + hi/lo planes; 2 = silu(gate)*up -> planes (smem-staged)
#define STG   32768
#define T_AL  8192
#define T_WH  16384
#define T_WL  24576

__global__ void __launch_bounds__(256, 2) gemm_mma(
    const unsigned short* __restrict__ Ah, const unsigned short* __restrict__ Al, int aDiv,
    const unsigned short* __restrict__ Wh, const unsigned short* __restrict__ Wl,
    float* __restrict__ C, int K, int N,
    unsigned short* __restrict__ Ph, unsigned short* __restrict__ Pl, int fuse)
{
    extern __shared__ __align__(1024) char sm[];
    uint32_t sb = smem_u32(sm);

    int tid = threadIdx.x;
    int wid = tid >> 5, lane = tid & 31;
    int wm = wid & 1, wn = wid >> 1;
    int pair = blockIdx.z;
    int m0 = blockIdx.x * 128, n0 = blockIdx.y * 128;

    const unsigned short* pAh = Ah + (long)(pair / aDiv) * Ss * K + (long)m0 * K;
    const unsigned short* pAl = Al + (long)(pair / aDiv) * Ss * K + (long)m0 * K;
    const unsigned short* pWh = Wh + (long)g_pair_e[pair] * N * K + (long)n0 * K;
    const unsigned short* pWl = Wl + (long)g_pair_e[pair] * N * K + (long)n0 * K;

    int r_ = tid >> 2, c_ = tid & 3;
    uint32_t so[2]; long go[2];
#pragma unroll
    for (int j = 0; j < 2; j++) {
        int row = r_ + 64 * j;
        so[j] = row * 64 + ((c_ ^ ((row >> 1) & 3)) << 4);
        go[j] = (long)row * K + c_ * 8;
    }

    int l8 = lane & 7;
    int rowA = l8 + 8 * ((lane >> 3) & 1);
    int cA = lane >> 4;
    int rowB = l8 + 8 * (lane >> 4);
    int cB = (lane >> 3) & 1;
    int swA = (rowA >> 1) & 3, swB = (rowB >> 1) & 3;
    uint32_t aOff = (uint32_t)(wm * 64 + rowA) * 64;
    uint32_t bOff = (uint32_t)(wn * 32 + rowB) * 64;

    float acc[4][4][4];
#pragma unroll
    for (int i = 0; i < 4; i++)
#pragma unroll
        for (int j = 0; j < 4; j++)
#pragma unroll
            for (int k = 0; k < 4; k++) acc[i][j][k] = 0.f;

    int nc = K >> 5;

#pragma unroll
    for (int s = 0; s < 2; s++) {
        uint32_t st = sb + s * STG;
        long kb = (long)s * 32;
#pragma unroll
        for (int j = 0; j < 2; j++) {
            CP_ASYNC(st + so[j],        pAh + go[j] + kb);
            CP_ASYNC(st + T_AL + so[j], pAl + go[j] + kb);
            CP_ASYNC(st + T_WH + so[j], pWh + go[j] + kb);
            CP_ASYNC(st + T_WL + so[j], pWl + go[j] + kb);
        }
        CP_COMMIT();
    }

    int sIdx = 0;
    for (int c = 0; c < nc; c++) {
        CP_WAIT1();
        __syncthreads();
        if (c + 2 < nc) {
            int s2 = sIdx + 2; if (s2 >= 3) s2 -= 3;
            uint32_t st = sb + s2 * STG;
            long kb = (long)(c + 2) * 32;
#pragma unroll
            for (int j = 0; j < 2; j++) {
                CP_ASYNC(st + so[j],        pAh + go[j] + kb);
                CP_ASYNC(st + T_AL + so[j], pAl + go[j] + kb);
                CP_ASYNC(st + T_WH + so[j], pWh + go[j] + kb);
                CP_ASYNC(st + T_WL + so[j], pWl + go[j] + kb);
            }
            CP_COMMIT();
        } else {
            CP_COMMIT();
        }

        uint32_t st = sb + sIdx * STG;
#pragma unroll
        for (int kk = 0; kk < 2; kk++) {
            uint32_t kxA = (uint32_t)(((2 * kk + cA) ^ swA) << 4);
            uint32_t kxB = (uint32_t)(((2 * kk + cB) ^ swB) << 4);
            unsigned af[4][4], bh[4][2], bl[4][2];
#pragma unroll
            for (int mt = 0; mt < 4; mt++)
                LDMX4(af[mt][0], af[mt][1], af[mt][2], af[mt][3], st + aOff + mt * 1024 + kxA);
            LDMX4(bh[0][0], bh[0][1], bh[1][0], bh[1][1], st + T_WH + bOff + kxB);
            LDMX4(bh[2][0], bh[2][1], bh[3][0], bh[3][1], st + T_WH + bOff + 1024 + kxB);
#pragma unroll
            for (int mt = 0; mt < 4; mt++) {
#pragma unroll
                for (int nt = 0; nt < 4; nt++)
                    MMA16816(acc[mt][nt], af[mt][0], af[mt][1], af[mt][2], af[mt][3], bh[nt][0], bh[nt][1]);
                if (mt == 0) { LDMX4(bl[0][0], bl[0][1], bl[1][0], bl[1][1], st + T_WL + bOff + kxB); }
                if (mt == 1) { LDMX4(bl[2][0], bl[2][1], bl[3][0], bl[3][1], st + T_WL + bOff + 1024 + kxB); }
            }
#pragma unroll
            for (int mt = 0; mt < 4; mt++) {
#pragma unroll
                for (int nt = 0; nt < 4; nt++)
                    MMA16816(acc[mt][nt], af[mt][0], af[mt][1], af[mt][2], af[mt][3], bl[nt][0], bl[nt][1]);
                LDMX4(af[mt][0], af[mt][1], af[mt][2], af[mt][3], st + T_AL + aOff + mt * 1024 + kxA);
            }
#pragma unroll
            for (int mt = 0; mt < 4; mt++)
#pragma unroll
                for (int nt = 0; nt < 4; nt++)
                    MMA16816(acc[mt][nt], af[mt][0], af[mt][1], af[mt][2], af[mt][3], bh[nt][0], bh[nt][1]);
        }
        sIdx++; if (sIdx >= 3) sIdx -= 3;
    }

    int g = lane >> 2, t2 = (lane & 3) * 2;
    if (fuse == 2) {
        __syncthreads();   // mainloop smem reads complete before overwrite
        unsigned short* sh = (unsigned short*)sm;
        unsigned short* sl = (unsigned short*)(sm + 16384);
#pragma unroll
        for (int mt = 0; mt < 4; mt++) {
            int ml = wm * 64 + mt * 16 + g;
#pragma unroll
            for (int nt = 0; nt < 4; nt++) {
                int jl = (wn * 32 + nt * 8 + t2) >> 1;
                float g0 = acc[mt][nt][0], u0 = acc[mt][nt][1];
                float g1 = acc[mt][nt][2], u1 = acc[mt][nt][3];
                float y0 = g0 / (1.f + expf(-g0)) * u0;
                float y1 = g1 / (1.f + expf(-g1)) * u1;
                unsigned short h, l;
                split2(y0, h, l); sh[ml * 64 + jl] = h; sl[ml * 64 + jl] = l;
                split2(y1, h, l); sh[(ml + 8) * 64 + jl] = h; sl[(ml + 8) * 64 + jl] = l;
            }
        }
        __syncthreads();
        int row = tid >> 1, half = tid & 1;
        int NH = N >> 1;   // = INTER
        long gbase = ((long)pair * Ss + m0 + row) * NH + (n0 >> 1) + half * 32;
        const uint4* s4h = (const uint4*)(sh + row * 64 + half * 32);
        const uint4* s4l = (const uint4*)(sl + row * 64 + half * 32);
#pragma unroll
        for (int q = 0; q < 4; q++) {
            *(uint4*)(Ph + gbase + q * 8) = s4h[q];
            *(uint4*)(Pl + gbase + q * 8) = s4l[q];
        }
    } else {
        float* Cp = C + (long)pair * Ss * N;
#pragma unroll
        for (int mt = 0; mt < 4; mt++) {
            int m = m0 + wm * 64 + mt * 16 + g;
#pragma unroll
            for (int nt = 0; nt < 4; nt++) {
                int n = n0 + wn * 32 + nt * 8 + t2;
                *(float2*)(Cp + (long)m * N + n)       = make_float2(acc[mt][nt][0], acc[mt][nt][1]);
                *(float2*)(Cp + (long)(m + 8) * N + n) = make_float2(acc[mt][nt][2], acc[mt][nt][3]);
                if (fuse == 1) {
                    long r0 = ((long)pair * Ss + m) * N + n;
                    long r1 = ((long)pair * Ss + m + 8) * N + n;
                    unsigned short h0, l0, h1, l1;
                    split2(acc[mt][nt][0], h0, l0); split2(acc[mt][nt][1], h1, l1);
                    *(unsigned*)(Ph + r0) = (unsigned)h0 | ((unsigned)h1 << 16);
                    *(unsigned*)(Pl + r0) = (unsigned)l0 | ((unsigned)l1 << 16);
                    split2(acc[mt][nt][2], h0, l0); split2(acc[mt][nt][3], h1, l1);
                    *(unsigned*)(Ph + r1) = (unsigned)h0 | ((unsigned)h1 << 16);
                    *(unsigned*)(Pl + r1) = (unsigned)l0 | ((unsigned)l1 << 16);
                }
            }
        }
    }
}

// ---------------- prep attention: rope + scale + hi/lo split + V transpose ----------------
__global__ void prep_attn(const float* __restrict__ cosb, const float* __restrict__ sinb) {
    int s = blockIdx.x, pair = blockIdx.y;
    int tid = threadIdx.x;
    int hh = tid >> 5, d = tid & 31;
    const float* base = g_qkv + ((long)pair * Ss + s) * QKVW;
    long ph = (long)pair * 8 + hh;
    float c1 = cosb[s * HD + d],      s1 = sinb[s * HD + d];
    float c2 = cosb[s * HD + d + 32], s2 = sinb[s * HD + d + 32];
    {
        float x1 = base[hh * HD + d], x2 = base[hh * HD + d + 32];
        float y1 = (x1 * c1 - x2 * s1) * 0.125f;
        float y2 = (x2 * c2 + x1 * s2) * 0.125f;
        long o = (ph * Ss + s) * HD + d;
        unsigned short h0, l0, h1, l1;
        split2(y1, h0, l0); split2(y2, h1, l1);
        g_aw[WQH + o] = h0; g_aw[WQL + o] = l0;
        g_aw[WQH + o + 32] = h1; g_aw[WQL + o + 32] = l1;
    }
    {
        float x1 = base[512 + hh * HD + d], x2 = base[512 + hh * HD + d + 32];
        float y1 = x1 * c1 - x2 * s1;
        float y2 = x2 * c2 + x1 * s2;
        long o = (ph * Ss + s) * HD + d;
        unsigned short h0, l0, h1, l1;
        split2(y1, h0, l0); split2(y2, h1, l1);
        g_aw[WKH + o] = h0; g_aw[WKL + o] = l0;
        g_aw[WKH + o + 32] = h1; g_aw[WKL + o + 32] = l1;
    }
    {
        float v1 = base[1024 + hh * HD + d], v2 = base[1024 + hh * HD + d + 32];
        long o1 = (ph * HD + d) * Ss + s;
        long o2 = (ph * HD + d + 32) * Ss + s;
        unsigned short h0, l0, h1, l1;
        split2(v1, h0, l0); split2(v2, h1, l1);
        g_aw[WVH + o1] = h0; g_aw[WVL + o1] = l0;
        g_aw[WVH + o2] = h1; g_aw[WVL + o2] = l1;
    }
}

// ---------------- mma flash attention ----------------
#define ASMEM 98304

__global__ void __launch_bounds__(256) attn_mma(unsigned short* __restrict__ Ph,
                                                unsigned short* __restrict__ Pl) {
    extern __shared__ __align__(1024) char sm2[];
    uint32_t sb = smem_u32(sm2);
    int tid = threadIdx.x, w = tid >> 5, lane = tid & 31;
    int qt = blockIdx.x, head = blockIdx.y, pair = blockIdx.z;
    int q0 = qt * 128;
    long ph = (long)pair * 8 + head;
    const unsigned short* Qh = g_aw + WQH + ph * Ss * HD;
    const unsigned short* Ql = g_aw + WQL + ph * Ss * HD;
    const unsigned short* Kh = g_aw + WKH + ph * Ss * HD;
    const unsigned short* Kl = g_aw + WKL + ph * Ss * HD;
    const unsigned short* Vh = g_aw + WVH + ph * HD * Ss;
    const unsigned short* Vl = g_aw + WVL + ph * HD * Ss;

    int ldRow = tid >> 3, ldC = tid & 7;

#pragma unroll
    for (int j = 0; j < 4; j++) {
        int row = ldRow + 32 * j;
        uint32_t so = row * 128 + ((ldC ^ (row & 7)) << 4);
        CP_ASYNC(sb + so,         Qh + (long)(q0 + row) * HD + ldC * 8);
        CP_ASYNC(sb + 16384 + so, Ql + (long)(q0 + row) * HD + ldC * 8);
    }
    auto issue = [&](int buf, int kt) {
        uint32_t st = sb + 32768 + buf * 32768;
#pragma unroll
        for (int j = 0; j < 2; j++) {
            int row = ldRow + 32 * j;
            uint32_t so = row * 128 + ((ldC ^ (row & 7)) << 4);
            long kOff = (long)(kt * 64 + row) * HD + ldC * 8;
            CP_ASYNC(st + so,         Kh + kOff);
            CP_ASYNC(st + 8192 + so,  Kl + kOff);
            long vOff = (long)row * Ss + kt * 64 + ldC * 8;
            CP_ASYNC(st + 16384 + so, Vh + vOff);
            CP_ASYNC(st + 24576 + so, Vl + vOff);
        }
    };
    issue(0, 0); CP_COMMIT();
    issue(1, 1); CP_COMMIT();

    int l8 = lane & 7;
    int rowA = l8 + 8 * ((lane >> 3) & 1);
    int cA = lane >> 4;
    int rowB = l8 + 8 * (lane >> 4);
    int cB = (lane >> 3) & 1;
    uint32_t aOff = (uint32_t)(w * 16 + rowA) * 128;
    uint32_t bOff = (uint32_t)rowB * 128;

    float o[8][4];
#pragma unroll
    for (int f = 0; f < 8; f++)
#pragma unroll
        for (int k = 0; k < 4; k++) o[f][k] = 0.f;
    float mr[2] = {-1e30f, -1e30f}, lr[2] = {0.f, 0.f};

    for (int kt = 0; kt < 8; kt++) {
        CP_WAIT1();
        __syncthreads();
        int buf = kt & 1;
        uint32_t st = sb + 32768 + buf * 32768;

        float sc[8][4];
#pragma unroll
        for (int f = 0; f < 8; f++)
#pragma unroll
            for (int k = 0; k < 4; k++) sc[f][k] = 0.f;
#pragma unroll
        for (int pass = 0; pass < 3; pass++) {
            uint32_t aB = sb + (pass == 1 ? 16384u : 0u) + aOff;
            uint32_t bB = st + (pass == 2 ? 8192u : 0u) + bOff;
#pragma unroll
            for (int kk = 0; kk < 4; kk++) {
                unsigned af[4], bfr[8][2];
                uint32_t kxA = (uint32_t)(((2 * kk + cA) ^ l8) << 4);
                uint32_t kxB = (uint32_t)(((2 * kk + cB) ^ l8) << 4);
                LDMX4(af[0], af[1], af[2], af[3], aB + kxA);
#pragma unroll
                for (int n2 = 0; n2 < 4; n2++)
                    LDMX4(bfr[2*n2][0], bfr[2*n2][1], bfr[2*n2+1][0], bfr[2*n2+1][1],
                          bB + n2 * 2048 + kxB);
#pragma unroll
                for (int nt = 0; nt < 8; nt++)
                    MMA16816(sc[nt], af[0], af[1], af[2], af[3], bfr[nt][0], bfr[nt][1]);
            }
        }

#pragma unroll
        for (int r = 0; r < 2; r++) {
            float mx = -1e30f;
#pragma unroll
            for (int f = 0; f < 8; f++) mx = fmaxf(mx, fmaxf(sc[f][2*r], sc[f][2*r+1]));
            mx = fmaxf(mx, __shfl_xor_sync(0xffffffffu, mx, 1));
            mx = fmaxf(mx, __shfl_xor_sync(0xffffffffu, mx, 2));
            float mn = fmaxf(mr[r], mx);
            float scale = expf(mr[r] - mn);
            mr[r] = mn;
            float ls = 0.f;
#pragma unroll
            for (int f = 0; f < 8; f++) {
                float p0 = expf(sc[f][2*r] - mn);
                float p1 = expf(sc[f][2*r+1] - mn);
                sc[f][2*r] = p0; sc[f][2*r+1] = p1;
                ls += p0 + p1;
            }
            ls += __shfl_xor_sync(0xffffffffu, ls, 1);
            ls += __shfl_xor_sync(0xffffffffu, ls, 2);
            lr[r] = lr[r] * scale + ls;
#pragma unroll
            for (int f = 0; f < 8; f++) { o[f][2*r] *= scale; o[f][2*r+1] *= scale; }
        }

        unsigned aPh[4][4], aPl[4][4];
#pragma unroll
        for (int j = 0; j < 4; j++) {
#pragma unroll
            for (int u = 0; u < 4; u++) {
                int f = 2 * j + (u >> 1);
                int c = (u & 1) * 2;
                unsigned short h0, l0, h1, l1;
                split2(sc[f][c], h0, l0);
                split2(sc[f][c + 1], h1, l1);
                aPh[j][u] = (unsigned)h0 | ((unsigned)h1 << 16);
                aPl[j][u] = (unsigned)l0 | ((unsigned)l1 << 16);
            }
        }

#pragma unroll
        for (int pass = 0; pass < 3; pass++) {
            uint32_t vB = st + (pass == 2 ? 24576u : 16384u) + bOff;
#pragma unroll
            for (int j = 0; j < 4; j++) {
                unsigned bfr[8][2];
                uint32_t kxB = (uint32_t)(((2 * j + cB) ^ l8) << 4);
#pragma unroll
                for (int n2 = 0; n2 < 4; n2++)
                    LDMX4(bfr[2*n2][0], bfr[2*n2][1], bfr[2*n2+1][0], bfr[2*n2+1][1],
                          vB + n2 * 2048 + kxB);
                const unsigned (*aP)[4] = (pass == 1) ? aPl : aPh;
#pragma unroll
                for (int nt = 0; nt < 8; nt++)
                    MMA16816(o[nt], aP[j][0], aP[j][1], aP[j][2], aP[j][3],
                             bfr[nt][0], bfr[nt][1]);
            }
        }
        __syncthreads();
        if (kt + 2 < 8) issue(buf, kt + 2);
        CP_COMMIT();
    }

    int g = lane >> 2, t2 = (lane & 3) * 2;
#pragma unroll
    for (int r = 0; r < 2; r++) {
        float inv = 1.f / lr[r];
        long row = (long)pair * Ss + q0 + w * 16 + g + 8 * r;
#pragma unroll
        for (int nt = 0; nt < 8; nt++) {
            float y0 = o[nt][2*r] * inv, y1 = o[nt][2*r+1] * inv;
            unsigned short h0, l0, h1, l1;
            split2(y0, h0, l0); split2(y1, h1, l1);
            long off = row * HSUB + head * HD + nt * 8 + t2;
            *(unsigned*)(Ph + off) = (unsigned)h0 | ((unsigned)h1 << 16);
            *(unsigned*)(Pl + off) = (unsigned)l0 | ((unsigned)l1 << 16);
        }
    }
}

// ---------------- residual + rmsnorm, warp-per-row, fused hi/lo split ----------------
// grid: NPAIR*Ss/8 blocks, 256 threads; warp w handles row blockIdx*8+w
__global__ void resnorm2_kernel(unsigned short* __restrict__ Ph, unsigned short* __restrict__ Pl) {
    int tid = threadIdx.x;
    long row = (long)blockIdx.x * 8 + (tid >> 5);
    int lane = tid & 31;
    float* a = g_hs + row * HSUB;
    const float* t = g_tmp + row * HSUB;
    float4 x4[4];
    float ss = 0.f;
#pragma unroll
    for (int q = 0; q < 4; q++) {
        float4 u = ((const float4*)a)[lane + 32 * q];
        float4 v = ((const float4*)t)[lane + 32 * q];
        x4[q] = make_float4(u.x + v.x, u.y + v.y, u.z + v.z, u.w + v.w);
        ss += x4[q].x * x4[q].x + x4[q].y * x4[q].y + x4[q].z * x4[q].z + x4[q].w * x4[q].w;
    }
#pragma unroll
    for (int off = 16; off; off >>= 1) ss += __shfl_xor_sync(0xffffffffu, ss, off);
    float scale = rsqrtf(ss * (1.f / HSUB) + 1e-5f);
#pragma unroll
    for (int q = 0; q < 4; q++) {
        float y[4] = {x4[q].x * scale, x4[q].y * scale, x4[q].z * scale, x4[q].w * scale};
        ((float4*)a)[lane + 32 * q] = make_float4(y[0], y[1], y[2], y[3]);
        unsigned int h[4], l[4];
#pragma unroll
        for (int j = 0; j < 4; j++) { unsigned short hs_, ls_; split2(y[j], hs_, ls_); h[j] = hs_; l[j] = ls_; }
        uint2 uh, ul;
        uh.x = h[0] | (h[1] << 16); uh.y = h[2] | (h[3] << 16);
        ul.x = l[0] | (l[1] << 16); ul.y = l[2] | (l[3] << 16);
        ((uint2*)(Ph + row * HSUB))[lane + 32 * q] = uh;
        ((uint2*)(Pl + row * HSUB))[lane + 32 * q] = ul;
    }
}

// ---------------- final ----------------
__global__ void final_kernel(float* __restrict__ out) {
    int b = blockIdx.y, s = blockIdx.x;
    float w0 = g_pair_w[2 * b], w1 = g_pair_w[2 * b + 1];
    long r = (long)b * Ss + s;
    const float* hp = g_h + r * Hh;
    const float* u0 = g_up + ((long)(2 * b) * Ss + s) * Hh;
    const float* u1 = g_up + ((long)(2 * b + 1) * Ss + s) * Hh;
    int tid = threadIdx.x;
    int c = tid * 4;
    float4 vh = *(const float4*)(hp + c);
    float4 v0 = *(const float4*)(u0 + c);
    float4 v1 = *(const float4*)(u1 + c);
    float y[4];
    y[0] = vh.x + w0 * v0.x + w1 * v1.x;
    y[1] = vh.y + w0 * v0.y + w1 * v1.y;
    y[2] = vh.z + w0 * v0.z + w1 * v1.z;
    y[3] = vh.w + w0 * v0.w + w1 * v1.w;
    float ss = y[0] * y[0] + y[1] * y[1] + y[2] * y[2] + y[3] * y[3];
#pragma unroll
    for (int off = 16; off; off >>= 1) ss += __shfl_xor_sync(0xffffffffu, ss, off);
    __shared__ float red[8];
    __shared__ float stot;
    if ((tid & 31) == 0) red[tid >> 5] = ss;
    __syncthreads();
    if (tid == 0) {
        float tsum = 0.f;
        for (int i = 0; i < 8; i++) tsum += red[i];
        stot = tsum;
    }
    __syncthreads();
    float scale = rsqrtf(stot * (1.f / Hh) + 1e-5f);
    float4 o;
    o.x = y[0] * scale; o.y = y[1] * scale; o.z = y[2] * scale; o.w = y[3] * scale;
    *(float4*)(out + r * Hh + c) = o;
}

// ---------------- launch ----------------
extern "C" void kernel_launch(void* const* d_in, const int* in_sizes, int n_in,
                              void* d_out, int out_size) {
    const float* hidden     = (const float*)d_in[0];
    const float* inj        = (const float*)d_in[1];
    const float* cosb       = (const float*)d_in[2];
    const float* sinb       = (const float*)d_in[3];
    const float* gate_w     = (const float*)d_in[4];
    const float* down_w     = (const float*)d_in[5];
    const float* up_w       = (const float*)d_in[6];
    const float* qkv_w      = (const float*)d_in[7];
    const float* o_w        = (const float*)d_in[8];
    const float* gate_up_w  = (const float*)d_in[9];
    const float* mlp_down_w = (const float*)d_in[10];
    float* out = (float*)d_out;

    void* vp;
    cudaGetSymbolAddress(&vp, g_hs);  float* p_hs  = (float*)vp;
    cudaGetSymbolAddress(&vp, g_qkv); float* p_qkv = (float*)vp;
    cudaGetSymbolAddress(&vp, g_tmp); float* p_tmp = (float*)vp;
    cudaGetSymbolAddress(&vp, g_up);  float* p_up  = (float*)vp;
    cudaGetSymbolAddress(&vp, g_wh);  unsigned short* p_wh = (unsigned short*)vp;
    cudaGetSymbolAddress(&vp, g_wl);  unsigned short* p_wl = (unsigned short*)vp;
    cudaGetSymbolAddress(&vp, g_p0h); unsigned short* p0h = (unsigned short*)vp;
    cudaGetSymbolAddress(&vp, g_p0l); unsigned short* p0l = (unsigned short*)vp;
    cudaGetSymbolAddress(&vp, g_p1h); unsigned short* p1h = (unsigned short*)vp;
    cudaGetSymbolAddress(&vp, g_p1l); unsigned short* p1l = (unsigned short*)vp;

    cudaFuncSetAttribute(gemm_mma, cudaFuncAttributeMaxDynamicSharedMemorySize, 3 * STG);
    cudaFuncSetAttribute(attn_mma, cudaFuncAttributeMaxDynamicSharedMemorySize, ASMEM);

    // all weights -> planes, one launch (gate_up rows interleaved)
    cvtw_kernel<<<34816, 256>>>(down_w, qkv_w, o_w, gate_up_w, mlp_down_w, up_w, p_wh, p_wl);

    // 1. h = hidden + injection (fused split into P0) ; routing
    add3_kernel<<<(Bb * Ss * Hh / 4) / 256, 256>>>(hidden, inj, p0h, p0l);
    routing_kernel<<<1, 512>>>(gate_w, out + (out_size - 1));

    // 2. hs0 = h @ down_w^T  (K=1024, N=512); planes -> P1
    gemm_mma<<<dim3(4, HSUB / 128, NPAIR), 256, 3 * STG>>>(
        p0h, p0l, 2, p_wh + OFF_DOWN, p_wl + OFF_DOWN, p_hs, Hh, HSUB, p1h, p1l, 1);

    // 3. qkv = hs0 @ qkv_w^T  (K=512, N=1536)
    gemm_mma<<<dim3(4, QKVW / 128, NPAIR), 256, 3 * STG>>>(
        p1h, p1l, 1, p_wh + OFF_QKV, p_wl + OFF_QKV, p_qkv, HSUB, QKVW,
        (unsigned short*)0, (unsigned short*)0, 0);

    // 4. prep + attention (planes -> P0)
    prep_attn<<<dim3(Ss, NPAIR), 256>>>(cosb, sinb);
    attn_mma<<<dim3(4, NHEAD, NPAIR), 256, ASMEM>>>(p0h, p0l);

    // 5. tmp = att @ o_w^T  (K=512, N=512)
    gemm_mma<<<dim3(4, HSUB / 128, NPAIR), 256, 3 * STG>>>(
        p0h, p0l, 1, p_wh + OFF_O, p_wl + OFF_O, p_tmp, HSUB, HSUB,
        (unsigned short*)0, (unsigned short*)0, 0);

    // 6. hs1 = rmsnorm(hs0 + tmp) -> planes P1
    resnorm2_kernel<<<NPAIR * Ss / 8, 256>>>(p1h, p1l);

    // 7+8. act = silu(gate)*up fused into gu GEMM epilogue (smem-staged) -> planes P0
    gemm_mma<<<dim3(4, GUW / 128, NPAIR), 256, 3 * STG>>>(
        p1h, p1l, 1, p_wh + OFF_GU, p_wl + OFF_GU, (float*)0, HSUB, GUW, p0h, p0l, 2);

    // 9. tmp = act @ mlp_down_w^T  (K=1536, N=512)
    gemm_mma<<<dim3(4, HSUB / 128, NPAIR), 256, 3 * STG>>>(
        p0h, p0l, 1, p_wh + OFF_MLPD, p_wl + OFF_MLPD, p_tmp, INTER, HSUB,
        (unsigned short*)0, (unsigned short*)0, 0);

    // 10. hs2 = rmsnorm(hs1 + tmp) -> planes P1
    resnorm2_kernel<<<NPAIR * Ss / 8, 256>>>(p1h, p1l);

    // 11. up_out = hs2 @ up_w^T  (K=512, N=1024)
    gemm_mma<<<dim3(4, Hh / 128, NPAIR), 256, 3 * STG>>>(
        p1h, p1l, 1, p_wh + OFF_UP, p_wl + OFF_UP, p_up, HSUB, Hh,
        (unsigned short*)0, (unsigned short*)0, 0);

    // 12. out = rmsnorm(h + w0*u0 + w1*u1)
    final_kernel<<<dim3(Ss, Bb), 256>>>(out);
}

// round 17
// speedup vs baseline: 1.0241x; 1.0001x over previous
#include <cuda_runtime.h>
#include <cuda_bf16.h>
#include <math.h>
#include <stdint.h>

#define Bb 8
#define Ss 512
#define Hh 1024
#define Ee 8
#define NHEAD 8
#define HD 64
#define HSUB 512
#define INTER 1536
#define NPAIR 16
#define QKVW 1536
#define GUW 3072

// ---------------- scratch ----------------
__device__ float g_h[Bb * Ss * Hh];
__device__ float g_hs[NPAIR * Ss * HSUB];
__device__ float g_qkv[NPAIR * Ss * QKVW];
__device__ float g_tmp[NPAIR * Ss * HSUB];
__device__ float g_up[NPAIR * Ss * Hh];
__device__ int   g_pair_e[NPAIR];
__device__ float g_pair_w[NPAIR];

#define OFF_DOWN 0L
#define OFF_QKV  4194304L
#define OFF_O    10485760L
#define OFF_GU   12582912L
#define OFF_MLPD 25165824L
#define OFF_UP   31457280L
#define W_TOTAL  35651584L
__device__ unsigned short g_wh[W_TOTAL];
__device__ unsigned short g_wl[W_TOTAL];
__device__ unsigned short g_p0h[NPAIR * Ss * INTER];
__device__ unsigned short g_p0l[NPAIR * Ss * INTER];
__device__ unsigned short g_p1h[NPAIR * Ss * INTER];
__device__ unsigned short g_p1l[NPAIR * Ss * INTER];
#define AWP 4194304L
__device__ unsigned short g_aw[6 * AWP];
#define WQH 0L
#define WQL (1*AWP)
#define WKH (2*AWP)
#define WKL (3*AWP)
#define WVH (4*AWP)
#define WVL (5*AWP)

// ---------------- PTX helpers ----------------
__device__ __forceinline__ uint32_t smem_u32(const void* p) {
    uint32_t a;
    asm("{ .reg .u64 t; cvta.to.shared.u64 t, %1; cvt.u32.u64 %0, t; }" : "=r"(a) : "l"(p));
    return a;
}
#define CP_ASYNC(sm, gp) asm volatile("cp.async.cg.shared.global [%0], [%1], 16;" :: "r"(sm), "l"(gp))
#define CP_COMMIT()      asm volatile("cp.async.commit_group;" ::: "memory")
#define CP_WAIT1()       asm volatile("cp.async.wait_group 1;" ::: "memory")
#define LDMX4(r0, r1, r2, r3, a) \
    asm volatile("ldmatrix.sync.aligned.m8n8.x4.shared.b16 {%0,%1,%2,%3}, [%4];" \
        : "=r"(r0), "=r"(r1), "=r"(r2), "=r"(r3) : "r"(a))
#define MMA16816(d, a0, a1, a2, a3, b0, b1) \
    asm volatile("mma.sync.aligned.m16n8k16.row.col.f32.bf16.bf16.f32 " \
        "{%0,%1,%2,%3}, {%4,%5,%6,%7}, {%8,%9}, {%0,%1,%2,%3};" \
        : "+f"((d)[0]), "+f"((d)[1]), "+f"((d)[2]), "+f"((d)[3]) \
        : "r"(a0), "r"(a1), "r"(a2), "r"(a3), "r"(b0), "r"(b1))

__device__ __forceinline__ void split2(float x, unsigned short& h, unsigned short& l) {
    __nv_bfloat16 hb = __float2bfloat16(x);
    h = __bfloat16_as_ushort(hb);
    l = __bfloat16_as_ushort(__float2bfloat16(x - __bfloat162float(hb)));
}

// ---------------- h = hidden + injection, fused hi/lo split ----------------
__global__ void add3_kernel(const float* __restrict__ a, const float* __restrict__ b,
                            unsigned short* __restrict__ hi, unsigned short* __restrict__ lo) {
    long i = (long)blockIdx.x * 256 + threadIdx.x;
    float4 va = ((const float4*)a)[i];
    float4 vb = ((const float4*)b)[i];
    float x[4] = {va.x + vb.x, va.y + vb.y, va.z + vb.z, va.w + vb.w};
    ((float4*)g_h)[i] = make_float4(x[0], x[1], x[2], x[3]);
    unsigned int h[4], l[4];
#pragma unroll
    for (int j = 0; j < 4; j++) { unsigned short hs_, ls_; split2(x[j], hs_, ls_); h[j] = hs_; l[j] = ls_; }
    uint2 uh, ul;
    uh.x = h[0] | (h[1] << 16); uh.y = h[2] | (h[3] << 16);
    ul.x = l[0] | (l[1] << 16); ul.y = l[2] | (l[3] << 16);
    ((uint2*)hi)[i] = uh; ((uint2*)lo)[i] = ul;
}

// ---------------- all weights -> 2 bf16 planes; gate_up rows interleaved ----------------
__global__ void cvtw_kernel(const float* __restrict__ p0, const float* __restrict__ p1,
                            const float* __restrict__ p2, const float* __restrict__ p3,
                            const float* __restrict__ p4, const float* __restrict__ p5,
                            unsigned short* __restrict__ hi, unsigned short* __restrict__ lo) {
    long i = (long)blockIdx.x * 256 + threadIdx.x;   // float4 index, total 8912896
    const float* src; long off;
    if (i < 1048576L)      { src = p0; off = 0L; }
    else if (i < 2621440L) { src = p1; off = 1048576L; }
    else if (i < 3145728L) { src = p2; off = 2621440L; }
    else if (i < 6291456L) { src = p3; off = 3145728L; }
    else if (i < 7864320L) { src = p4; off = 6291456L; }
    else                   { src = p5; off = 7864320L; }
    float4 v = ((const float4*)src)[i - off];
    float x[4] = {v.x, v.y, v.z, v.w};
    unsigned int h[4], l[4];
#pragma unroll
    for (int j = 0; j < 4; j++) { unsigned short hs_, ls_; split2(x[j], hs_, ls_); h[j] = hs_; l[j] = ls_; }
    uint2 uh, ul;
    uh.x = h[0] | (h[1] << 16); uh.y = h[2] | (h[3] << 16);
    ul.x = l[0] | (l[1] << 16); ul.y = l[2] | (l[3] << 16);
    long di = i;
    if (i >= 3145728L && i < 6291456L) {
        long idx4 = i - 3145728L;
        long exp_ = idx4 / 393216L;          // per-expert: 3072*512/4 float4
        long rem = idx4 - exp_ * 393216L;
        long row = rem >> 7;                  // 128 float4 per 512-col row
        long col4 = rem & 127;
        long nrow = (row < 1536) ? 2 * row : 2 * (row - 1536) + 1;
        di = 3145728L + exp_ * 393216L + nrow * 128 + col4;
    }
    ((uint2*)hi)[di] = uh; ((uint2*)lo)[di] = ul;
}

// ---------------- routing: parallel logits, then top-2 ----------------
__global__ void routing_kernel(const float* __restrict__ gate_w, float* __restrict__ aux_out) {
    __shared__ float logits[Bb][Ee];
    __shared__ float probs[Bb][Ee];
    int tid = threadIdx.x;                 // 512 threads
    {
        int pairBE = tid >> 3;
        int sub = tid & 7;
        int b = pairBE >> 3, e = pairBE & 7;
        const float* hv = g_h + (long)b * Ss * Hh;
        const float* w = gate_w + e * Hh;
        float acc = 0.f;
#pragma unroll 4
        for (int i = sub; i < Hh; i += 8) acc += hv[i] * w[i];
        acc += __shfl_xor_sync(0xffffffffu, acc, 1);
        acc += __shfl_xor_sync(0xffffffffu, acc, 2);
        acc += __shfl_xor_sync(0xffffffffu, acc, 4);
        if (sub == 0) logits[b][e] = acc;
    }
    __syncthreads();
    if (tid < Bb) {
        int b = tid;
        float mx = -1e30f;
        for (int e = 0; e < Ee; e++) mx = fmaxf(mx, logits[b][e]);
        float p[Ee]; float sum = 0.f;
        for (int e = 0; e < Ee; e++) { p[e] = expf(logits[b][e] - mx); sum += p[e]; }
        for (int e = 0; e < Ee; e++) { p[e] /= sum; probs[b][e] = p[e]; }
        int i1 = 0;
        for (int e = 1; e < Ee; e++) if (p[e] > p[i1]) i1 = e;
        int i2 = -1; float v2 = -1e30f;
        for (int e = 0; e < Ee; e++) if (e != i1 && p[e] > v2) { v2 = p[e]; i2 = e; }
        float denom = fmaxf(p[i1] + v2, 1e-8f);
        g_pair_e[2 * b]     = i1; g_pair_w[2 * b]     = p[i1] / denom;
        g_pair_e[2 * b + 1] = i2; g_pair_w[2 * b + 1] = v2 / denom;
    }
    __syncthreads();
    if (tid == 0) {
        float aux = 0.f;
        for (int e = 0; e < Ee; e++) {
            float imp = 0.f;
            for (int b = 0; b < Bb; b++) imp += probs[b][e];
            imp /= (float)Bb;
            int cnt = 0;
            for (int p = 0; p < NPAIR; p++) if (g_pair_e[p] == e) cnt++;
            float loadf = (float)cnt / (float)(Bb * 2);
            aux += (float)Ee * imp * loadf;
        }
        *aux_out = aux;
    }
}

// ---------------- 4-tile mma GEMM, 3-term exact bf16, BK=32, 3-stage, pipelined ----------------
// fuse: 0 = write C only; 1 = write C + hi/lo planes; 2 = silu(gate)*up -> planes (smem-staged)
#define STG   32768
#define T_AL  8192
#define T_WH  16384
#define T_WL  24576

__global__ void __launch_bounds__(256, 2) gemm_mma(
    const unsigned short* __restrict__ Ah, const unsigned short* __restrict__ Al, int aDiv,
    const unsigned short* __restrict__ Wh, const unsigned short* __restrict__ Wl,
    float* __restrict__ C, int K, int N,
    unsigned short* __restrict__ Ph, unsigned short* __restrict__ Pl, int fuse)
{
    extern __shared__ __align__(1024) char sm[];
    uint32_t sb = smem_u32(sm);

    int tid = threadIdx.x;
    int wid = tid >> 5, lane = tid & 31;
    int wm = wid & 1, wn = wid >> 1;
    int pair = blockIdx.z;
    int m0 = blockIdx.x * 128, n0 = blockIdx.y * 128;

    const unsigned short* pAh = Ah + (long)(pair / aDiv) * Ss * K + (long)m0 * K;
    const unsigned short* pAl = Al + (long)(pair / aDiv) * Ss * K + (long)m0 * K;
    const unsigned short* pWh = Wh + (long)g_pair_e[pair] * N * K + (long)n0 * K;
    const unsigned short* pWl = Wl + (long)g_pair_e[pair] * N * K + (long)n0 * K;

    int r_ = tid >> 2, c_ = tid & 3;
    uint32_t so[2]; long go[2];
#pragma unroll
    for (int j = 0; j < 2; j++) {
        int row = r_ + 64 * j;
        so[j] = row * 64 + ((c_ ^ ((row >> 1) & 3)) << 4);
        go[j] = (long)row * K + c_ * 8;
    }

    int l8 = lane & 7;
    int rowA = l8 + 8 * ((lane >> 3) & 1);
    int cA = lane >> 4;
    int rowB = l8 + 8 * (lane >> 4);
    int cB = (lane >> 3) & 1;
    int swA = (rowA >> 1) & 3, swB = (rowB >> 1) & 3;
    uint32_t aOff = (uint32_t)(wm * 64 + rowA) * 64;
    uint32_t bOff = (uint32_t)(wn * 32 + rowB) * 64;

    float acc[4][4][4];
#pragma unroll
    for (int i = 0; i < 4; i++)
#pragma unroll
        for (int j = 0; j < 4; j++)
#pragma unroll
            for (int k = 0; k < 4; k++) acc[i][j][k] = 0.f;

    int nc = K >> 5;

#pragma unroll
    for (int s = 0; s < 2; s++) {
        uint32_t st = sb + s * STG;
        long kb = (long)s * 32;
#pragma unroll
        for (int j = 0; j < 2; j++) {
            CP_ASYNC(st + so[j],        pAh + go[j] + kb);
            CP_ASYNC(st + T_AL + so[j], pAl + go[j] + kb);
            CP_ASYNC(st + T_WH + so[j], pWh + go[j] + kb);
            CP_ASYNC(st + T_WL + so[j], pWl + go[j] + kb);
        }
        CP_COMMIT();
    }

    int sIdx = 0;
    for (int c = 0; c < nc; c++) {
        CP_WAIT1();
        __syncthreads();
        if (c + 2 < nc) {
            int s2 = sIdx + 2; if (s2 >= 3) s2 -= 3;
            uint32_t st = sb + s2 * STG;
            long kb = (long)(c + 2) * 32;
#pragma unroll
            for (int j = 0; j < 2; j++) {
                CP_ASYNC(st + so[j],        pAh + go[j] + kb);
                CP_ASYNC(st + T_AL + so[j], pAl + go[j] + kb);
                CP_ASYNC(st + T_WH + so[j], pWh + go[j] + kb);
                CP_ASYNC(st + T_WL + so[j], pWl + go[j] + kb);
            }
            CP_COMMIT();
        } else {
            CP_COMMIT();
        }

        uint32_t st = sb + sIdx * STG;
#pragma unroll
        for (int kk = 0; kk < 2; kk++) {
            uint32_t kxA = (uint32_t)(((2 * kk + cA) ^ swA) << 4);
            uint32_t kxB = (uint32_t)(((2 * kk + cB) ^ swB) << 4);
            unsigned af[4][4], bh[4][2], bl[4][2];
#pragma unroll
            for (int mt = 0; mt < 4; mt++)
                LDMX4(af[mt][0], af[mt][1], af[mt][2], af[mt][3], st + aOff + mt * 1024 + kxA);
            LDMX4(bh[0][0], bh[0][1], bh[1][0], bh[1][1], st + T_WH + bOff + kxB);
            LDMX4(bh[2][0], bh[2][1], bh[3][0], bh[3][1], st + T_WH + bOff + 1024 + kxB);
#pragma unroll
            for (int mt = 0; mt < 4; mt++) {
#pragma unroll
                for (int nt = 0; nt < 4; nt++)
                    MMA16816(acc[mt][nt], af[mt][0], af[mt][1], af[mt][2], af[mt][3], bh[nt][0], bh[nt][1]);
                if (mt == 0) { LDMX4(bl[0][0], bl[0][1], bl[1][0], bl[1][1], st + T_WL + bOff + kxB); }
                if (mt == 1) { LDMX4(bl[2][0], bl[2][1], bl[3][0], bl[3][1], st + T_WL + bOff + 1024 + kxB); }
            }
#pragma unroll
            for (int mt = 0; mt < 4; mt++) {
#pragma unroll
                for (int nt = 0; nt < 4; nt++)
                    MMA16816(acc[mt][nt], af[mt][0], af[mt][1], af[mt][2], af[mt][3], bl[nt][0], bl[nt][1]);
                LDMX4(af[mt][0], af[mt][1], af[mt][2], af[mt][3], st + T_AL + aOff + mt * 1024 + kxA);
            }
#pragma unroll
            for (int mt = 0; mt < 4; mt++)
#pragma unroll
                for (int nt = 0; nt < 4; nt++)
                    MMA16816(acc[mt][nt], af[mt][0], af[mt][1], af[mt][2], af[mt][3], bh[nt][0], bh[nt][1]);
        }
        sIdx++; if (sIdx >= 3) sIdx -= 3;
    }

    int g = lane >> 2, t2 = (lane & 3) * 2;
    if (fuse == 2) {
        __syncthreads();   // mainloop smem reads complete before overwrite
        unsigned short* sh = (unsigned short*)sm;
        unsigned short* sl = (unsigned short*)(sm + 16384);
#pragma unroll
        for (int mt = 0; mt < 4; mt++) {
            int ml = wm * 64 + mt * 16 + g;
#pragma unroll
            for (int nt = 0; nt < 4; nt++) {
                int jl = (wn * 32 + nt * 8 + t2) >> 1;
                float g0 = acc[mt][nt][0], u0 = acc[mt][nt][1];
                float g1 = acc[mt][nt][2], u1 = acc[mt][nt][3];
                float y0 = g0 / (1.f + expf(-g0)) * u0;
                float y1 = g1 / (1.f + expf(-g1)) * u1;
                unsigned short h, l;
                split2(y0, h, l); sh[ml * 64 + jl] = h; sl[ml * 64 + jl] = l;
                split2(y1, h, l); sh[(ml + 8) * 64 + jl] = h; sl[(ml + 8) * 64 + jl] = l;
            }
        }
        __syncthreads();
        int row = tid >> 1, half = tid & 1;
        int NH = N >> 1;   // = INTER
        long gbase = ((long)pair * Ss + m0 + row) * NH + (n0 >> 1) + half * 32;
        const uint4* s4h = (const uint4*)(sh + row * 64 + half * 32);
        const uint4* s4l = (const uint4*)(sl + row * 64 + half * 32);
#pragma unroll
        for (int q = 0; q < 4; q++) {
            *(uint4*)(Ph + gbase + q * 8) = s4h[q];
            *(uint4*)(Pl + gbase + q * 8) = s4l[q];
        }
    } else {
        float* Cp = C + (long)pair * Ss * N;
#pragma unroll
        for (int mt = 0; mt < 4; mt++) {
            int m = m0 + wm * 64 + mt * 16 + g;
#pragma unroll
            for (int nt = 0; nt < 4; nt++) {
                int n = n0 + wn * 32 + nt * 8 + t2;
                *(float2*)(Cp + (long)m * N + n)       = make_float2(acc[mt][nt][0], acc[mt][nt][1]);
                *(float2*)(Cp + (long)(m + 8) * N + n) = make_float2(acc[mt][nt][2], acc[mt][nt][3]);
                if (fuse == 1) {
                    long r0 = ((long)pair * Ss + m) * N + n;
                    long r1 = ((long)pair * Ss + m + 8) * N + n;
                    unsigned short h0, l0, h1, l1;
                    split2(acc[mt][nt][0], h0, l0); split2(acc[mt][nt][1], h1, l1);
                    *(unsigned*)(Ph + r0) = (unsigned)h0 | ((unsigned)h1 << 16);
                    *(unsigned*)(Pl + r0) = (unsigned)l0 | ((unsigned)l1 << 16);
                    split2(acc[mt][nt][2], h0, l0); split2(acc[mt][nt][3], h1, l1);
                    *(unsigned*)(Ph + r1) = (unsigned)h0 | ((unsigned)h1 << 16);
                    *(unsigned*)(Pl + r1) = (unsigned)l0 | ((unsigned)l1 << 16);
                }
            }
        }
    }
}

// ---------------- prep attention: rope + scale + hi/lo split + V transpose ----------------
__global__ void prep_attn(const float* __restrict__ cosb, const float* __restrict__ sinb) {
    int s = blockIdx.x, pair = blockIdx.y;
    int tid = threadIdx.x;
    int hh = tid >> 5, d = tid & 31;
    const float* base = g_qkv + ((long)pair * Ss + s) * QKVW;
    long ph = (long)pair * 8 + hh;
    float c1 = cosb[s * HD + d],      s1 = sinb[s * HD + d];
    float c2 = cosb[s * HD + d + 32], s2 = sinb[s * HD + d + 32];
    {
        float x1 = base[hh * HD + d], x2 = base[hh * HD + d + 32];
        float y1 = (x1 * c1 - x2 * s1) * 0.125f;
        float y2 = (x2 * c2 + x1 * s2) * 0.125f;
        long o = (ph * Ss + s) * HD + d;
        unsigned short h0, l0, h1, l1;
        split2(y1, h0, l0); split2(y2, h1, l1);
        g_aw[WQH + o] = h0; g_aw[WQL + o] = l0;
        g_aw[WQH + o + 32] = h1; g_aw[WQL + o + 32] = l1;
    }
    {
        float x1 = base[512 + hh * HD + d], x2 = base[512 + hh * HD + d + 32];
        float y1 = x1 * c1 - x2 * s1;
        float y2 = x2 * c2 + x1 * s2;
        long o = (ph * Ss + s) * HD + d;
        unsigned short h0, l0, h1, l1;
        split2(y1, h0, l0); split2(y2, h1, l1);
        g_aw[WKH + o] = h0; g_aw[WKL + o] = l0;
        g_aw[WKH + o + 32] = h1; g_aw[WKL + o + 32] = l1;
    }
    {
        float v1 = base[1024 + hh * HD + d], v2 = base[1024 + hh * HD + d + 32];
        long o1 = (ph * HD + d) * Ss + s;
        long o2 = (ph * HD + d + 32) * Ss + s;
        unsigned short h0, l0, h1, l1;
        split2(v1, h0, l0); split2(v2, h1, l1);
        g_aw[WVH + o1] = h0; g_aw[WVL + o1] = l0;
        g_aw[WVH + o2] = h1; g_aw[WVL + o2] = l1;
    }
}

// ---------------- mma flash attention ----------------
#define ASMEM 98304

__global__ void __launch_bounds__(256) attn_mma(unsigned short* __restrict__ Ph,
                                                unsigned short* __restrict__ Pl) {
    extern __shared__ __align__(1024) char sm2[];
    uint32_t sb = smem_u32(sm2);
    int tid = threadIdx.x, w = tid >> 5, lane = tid & 31;
    int qt = blockIdx.x, head = blockIdx.y, pair = blockIdx.z;
    int q0 = qt * 128;
    long ph = (long)pair * 8 + head;
    const unsigned short* Qh = g_aw + WQH + ph * Ss * HD;
    const unsigned short* Ql = g_aw + WQL + ph * Ss * HD;
    const unsigned short* Kh = g_aw + WKH + ph * Ss * HD;
    const unsigned short* Kl = g_aw + WKL + ph * Ss * HD;
    const unsigned short* Vh = g_aw + WVH + ph * HD * Ss;
    const unsigned short* Vl = g_aw + WVL + ph * HD * Ss;

    int ldRow = tid >> 3, ldC = tid & 7;

#pragma unroll
    for (int j = 0; j < 4; j++) {
        int row = ldRow + 32 * j;
        uint32_t so = row * 128 + ((ldC ^ (row & 7)) << 4);
        CP_ASYNC(sb + so,         Qh + (long)(q0 + row) * HD + ldC * 8);
        CP_ASYNC(sb + 16384 + so, Ql + (long)(q0 + row) * HD + ldC * 8);
    }
    auto issue = [&](int buf, int kt) {
        uint32_t st = sb + 32768 + buf * 32768;
#pragma unroll
        for (int j = 0; j < 2; j++) {
            int row = ldRow + 32 * j;
            uint32_t so = row * 128 + ((ldC ^ (row & 7)) << 4);
            long kOff = (long)(kt * 64 + row) * HD + ldC * 8;
            CP_ASYNC(st + so,         Kh + kOff);
            CP_ASYNC(st + 8192 + so,  Kl + kOff);
            long vOff = (long)row * Ss + kt * 64 + ldC * 8;
            CP_ASYNC(st + 16384 + so, Vh + vOff);
            CP_ASYNC(st + 24576 + so, Vl + vOff);
        }
    };
    issue(0, 0); CP_COMMIT();
    issue(1, 1); CP_COMMIT();

    int l8 = lane & 7;
    int rowA = l8 + 8 * ((lane >> 3) & 1);
    int cA = lane >> 4;
    int rowB = l8 + 8 * (lane >> 4);
    int cB = (lane >> 3) & 1;
    uint32_t aOff = (uint32_t)(w * 16 + rowA) * 128;
    uint32_t bOff = (uint32_t)rowB * 128;

    float o[8][4];
#pragma unroll
    for (int f = 0; f < 8; f++)
#pragma unroll
        for (int k = 0; k < 4; k++) o[f][k] = 0.f;
    float mr[2] = {-1e30f, -1e30f}, lr[2] = {0.f, 0.f};

    for (int kt = 0; kt < 8; kt++) {
        CP_WAIT1();
        __syncthreads();
        int buf = kt & 1;
        uint32_t st = sb + 32768 + buf * 32768;

        float sc[8][4];
#pragma unroll
        for (int f = 0; f < 8; f++)
#pragma unroll
            for (int k = 0; k < 4; k++) sc[f][k] = 0.f;
#pragma unroll
        for (int pass = 0; pass < 3; pass++) {
            uint32_t aB = sb + (pass == 1 ? 16384u : 0u) + aOff;
            uint32_t bB = st + (pass == 2 ? 8192u : 0u) + bOff;
#pragma unroll
            for (int kk = 0; kk < 4; kk++) {
                unsigned af[4], bfr[8][2];
                uint32_t kxA = (uint32_t)(((2 * kk + cA) ^ l8) << 4);
                uint32_t kxB = (uint32_t)(((2 * kk + cB) ^ l8) << 4);
                LDMX4(af[0], af[1], af[2], af[3], aB + kxA);
#pragma unroll
                for (int n2 = 0; n2 < 4; n2++)
                    LDMX4(bfr[2*n2][0], bfr[2*n2][1], bfr[2*n2+1][0], bfr[2*n2+1][1],
                          bB + n2 * 2048 + kxB);
#pragma unroll
                for (int nt = 0; nt < 8; nt++)
                    MMA16816(sc[nt], af[0], af[1], af[2], af[3], bfr[nt][0], bfr[nt][1]);
            }
        }

#pragma unroll
        for (int r = 0; r < 2; r++) {
            float mx = -1e30f;
#pragma unroll
            for (int f = 0; f < 8; f++) mx = fmaxf(mx, fmaxf(sc[f][2*r], sc[f][2*r+1]));
            mx = fmaxf(mx, __shfl_xor_sync(0xffffffffu, mx, 1));
            mx = fmaxf(mx, __shfl_xor_sync(0xffffffffu, mx, 2));
            float mn = fmaxf(mr[r], mx);
            float scale = expf(mr[r] - mn);
            mr[r] = mn;
            float ls = 0.f;
#pragma unroll
            for (int f = 0; f < 8; f++) {
                float p0 = expf(sc[f][2*r] - mn);
                float p1 = expf(sc[f][2*r+1] - mn);
                sc[f][2*r] = p0; sc[f][2*r+1] = p1;
                ls += p0 + p1;
            }
            ls += __shfl_xor_sync(0xffffffffu, ls, 1);
            ls += __shfl_xor_sync(0xffffffffu, ls, 2);
            lr[r] = lr[r] * scale + ls;
#pragma unroll
            for (int f = 0; f < 8; f++) { o[f][2*r] *= scale; o[f][2*r+1] *= scale; }
        }

        unsigned aPh[4][4], aPl[4][4];
#pragma unroll
        for (int j = 0; j < 4; j++) {
#pragma unroll
            for (int u = 0; u < 4; u++) {
                int f = 2 * j + (u >> 1);
                int c = (u & 1) * 2;
                unsigned short h0, l0, h1, l1;
                split2(sc[f][c], h0, l0);
                split2(sc[f][c + 1], h1, l1);
                aPh[j][u] = (unsigned)h0 | ((unsigned)h1 << 16);
                aPl[j][u] = (unsigned)l0 | ((unsigned)l1 << 16);
            }
        }

#pragma unroll
        for (int pass = 0; pass < 3; pass++) {
            uint32_t vB = st + (pass == 2 ? 24576u : 16384u) + bOff;
#pragma unroll
            for (int j = 0; j < 4; j++) {
                unsigned bfr[8][2];
                uint32_t kxB = (uint32_t)(((2 * j + cB) ^ l8) << 4);
#pragma unroll
                for (int n2 = 0; n2 < 4; n2++)
                    LDMX4(bfr[2*n2][0], bfr[2*n2][1], bfr[2*n2+1][0], bfr[2*n2+1][1],
                          vB + n2 * 2048 + kxB);
                const unsigned (*aP)[4] = (pass == 1) ? aPl : aPh;
#pragma unroll
                for (int nt = 0; nt < 8; nt++)
                    MMA16816(o[nt], aP[j][0], aP[j][1], aP[j][2], aP[j][3],
                             bfr[nt][0], bfr[nt][1]);
            }
        }
        __syncthreads();
        if (kt + 2 < 8) issue(buf, kt + 2);
        CP_COMMIT();
    }

    int g = lane >> 2, t2 = (lane & 3) * 2;
#pragma unroll
    for (int r = 0; r < 2; r++) {
        float inv = 1.f / lr[r];
        long row = (long)pair * Ss + q0 + w * 16 + g + 8 * r;
#pragma unroll
        for (int nt = 0; nt < 8; nt++) {
            float y0 = o[nt][2*r] * inv, y1 = o[nt][2*r+1] * inv;
            unsigned short h0, l0, h1, l1;
            split2(y0, h0, l0); split2(y1, h1, l1);
            long off = row * HSUB + head * HD + nt * 8 + t2;
            *(unsigned*)(Ph + off) = (unsigned)h0 | ((unsigned)h1 << 16);
            *(unsigned*)(Pl + off) = (unsigned)l0 | ((unsigned)l1 << 16);
        }
    }
}

// ---------------- residual + rmsnorm, warp-per-row, fused hi/lo split ----------------
__global__ void resnorm2_kernel(unsigned short* __restrict__ Ph, unsigned short* __restrict__ Pl) {
    int tid = threadIdx.x;
    long row = (long)blockIdx.x * 8 + (tid >> 5);
    int lane = tid & 31;
    float* a = g_hs + row * HSUB;
    const float* t = g_tmp + row * HSUB;
    float4 x4[4];
    float ss = 0.f;
#pragma unroll
    for (int q = 0; q < 4; q++) {
        float4 u = ((const float4*)a)[lane + 32 * q];
        float4 v = ((const float4*)t)[lane + 32 * q];
        x4[q] = make_float4(u.x + v.x, u.y + v.y, u.z + v.z, u.w + v.w);
        ss += x4[q].x * x4[q].x + x4[q].y * x4[q].y + x4[q].z * x4[q].z + x4[q].w * x4[q].w;
    }
#pragma unroll
    for (int off = 16; off; off >>= 1) ss += __shfl_xor_sync(0xffffffffu, ss, off);
    float scale = rsqrtf(ss * (1.f / HSUB) + 1e-5f);
#pragma unroll
    for (int q = 0; q < 4; q++) {
        float y[4] = {x4[q].x * scale, x4[q].y * scale, x4[q].z * scale, x4[q].w * scale};
        ((float4*)a)[lane + 32 * q] = make_float4(y[0], y[1], y[2], y[3]);
        unsigned int h[4], l[4];
#pragma unroll
        for (int j = 0; j < 4; j++) { unsigned short hs_, ls_; split2(y[j], hs_, ls_); h[j] = hs_; l[j] = ls_; }
        uint2 uh, ul;
        uh.x = h[0] | (h[1] << 16); uh.y = h[2] | (h[3] << 16);
        ul.x = l[0] | (l[1] << 16); ul.y = l[2] | (l[3] << 16);
        ((uint2*)(Ph + row * HSUB))[lane + 32 * q] = uh;
        ((uint2*)(Pl + row * HSUB))[lane + 32 * q] = ul;
    }
}

// ---------------- final: warp-per-row (8 rows/block), zero block barriers ----------------
__global__ void final_kernel(float* __restrict__ out) {
    int tid = threadIdx.x;
    long r = (long)blockIdx.x * 8 + (tid >> 5);   // row over Bb*Ss = 4096
    int lane = tid & 31;
    int b = (int)(r >> 9);                        // r / Ss
    float w0 = g_pair_w[2 * b], w1 = g_pair_w[2 * b + 1];
    const float* hp = g_h + r * Hh;
    const float* u0 = g_up + (r + (long)b * Ss) * Hh;        // (2b)*Ss + s
    const float* u1 = g_up + (r + (long)(b + 1) * Ss) * Hh;  // (2b+1)*Ss + s
    float4 y4[8];
    float ss = 0.f;
#pragma unroll
    for (int q = 0; q < 8; q++) {
        float4 vh = ((const float4*)hp)[lane + 32 * q];
        float4 v0 = ((const float4*)u0)[lane + 32 * q];
        float4 v1 = ((const float4*)u1)[lane + 32 * q];
        y4[q].x = vh.x + w0 * v0.x + w1 * v1.x;
        y4[q].y = vh.y + w0 * v0.y + w1 * v1.y;
        y4[q].z = vh.z + w0 * v0.z + w1 * v1.z;
        y4[q].w = vh.w + w0 * v0.w + w1 * v1.w;
        ss += y4[q].x * y4[q].x + y4[q].y * y4[q].y + y4[q].z * y4[q].z + y4[q].w * y4[q].w;
    }
#pragma unroll
    for (int off = 16; off; off >>= 1) ss += __shfl_xor_sync(0xffffffffu, ss, off);
    float scale = rsqrtf(ss * (1.f / Hh) + 1e-5f);
#pragma unroll
    for (int q = 0; q < 8; q++) {
        float4 o;
        o.x = y4[q].x * scale; o.y = y4[q].y * scale;
        o.z = y4[q].z * scale; o.w = y4[q].w * scale;
        ((float4*)(out + r * Hh))[lane + 32 * q] = o;
    }
}

// ---------------- launch ----------------
extern "C" void kernel_launch(void* const* d_in, const int* in_sizes, int n_in,
                              void* d_out, int out_size) {
    const float* hidden     = (const float*)d_in[0];
    const float* inj        = (const float*)d_in[1];
    const float* cosb       = (const float*)d_in[2];
    const float* sinb       = (const float*)d_in[3];
    const float* gate_w     = (const float*)d_in[4];
    const float* down_w     = (const float*)d_in[5];
    const float* up_w       = (const float*)d_in[6];
    const float* qkv_w      = (const float*)d_in[7];
    const float* o_w        = (const float*)d_in[8];
    const float* gate_up_w  = (const float*)d_in[9];
    const float* mlp_down_w = (const float*)d_in[10];
    float* out = (float*)d_out;

    void* vp;
    cudaGetSymbolAddress(&vp, g_hs);  float* p_hs  = (float*)vp;
    cudaGetSymbolAddress(&vp, g_qkv); float* p_qkv = (float*)vp;
    cudaGetSymbolAddress(&vp, g_tmp); float* p_tmp = (float*)vp;
    cudaGetSymbolAddress(&vp, g_up);  float* p_up  = (float*)vp;
    cudaGetSymbolAddress(&vp, g_wh);  unsigned short* p_wh = (unsigned short*)vp;
    cudaGetSymbolAddress(&vp, g_wl);  unsigned short* p_wl = (unsigned short*)vp;
    cudaGetSymbolAddress(&vp, g_p0h); unsigned short* p0h = (unsigned short*)vp;
    cudaGetSymbolAddress(&vp, g_p0l); unsigned short* p0l = (unsigned short*)vp;
    cudaGetSymbolAddress(&vp, g_p1h); unsigned short* p1h = (unsigned short*)vp;
    cudaGetSymbolAddress(&vp, g_p1l); unsigned short* p1l = (unsigned short*)vp;

    cudaFuncSetAttribute(gemm_mma, cudaFuncAttributeMaxDynamicSharedMemorySize, 3 * STG);
    cudaFuncSetAttribute(attn_mma, cudaFuncAttributeMaxDynamicSharedMemorySize, ASMEM);

    // all weights -> planes, one launch (gate_up rows interleaved)
    cvtw_kernel<<<34816, 256>>>(down_w, qkv_w, o_w, gate_up_w, mlp_down_w, up_w, p_wh, p_wl);

    // 1. h = hidden + injection (fused split into P0) ; routing
    add3_kernel<<<(Bb * Ss * Hh / 4) / 256, 256>>>(hidden, inj, p0h, p0l);
    routing_kernel<<<1, 512>>>(gate_w, out + (out_size - 1));

    // 2. hs0 = h @ down_w^T  (K=1024, N=512); planes -> P1
    gemm_mma<<<dim3(4, HSUB / 128, NPAIR), 256, 3 * STG>>>(
        p0h, p0l, 2, p_wh + OFF_DOWN, p_wl + OFF_DOWN, p_hs, Hh, HSUB, p1h, p1l, 1);

    // 3. qkv = hs0 @ qkv_w^T  (K=512, N=1536)
    gemm_mma<<<dim3(4, QKVW / 128, NPAIR), 256, 3 * STG>>>(
        p1h, p1l, 1, p_wh + OFF_QKV, p_wl + OFF_QKV, p_qkv, HSUB, QKVW,
        (unsigned short*)0, (unsigned short*)0, 0);

    // 4. prep + attention (planes -> P0)
    prep_attn<<<dim3(Ss, NPAIR), 256>>>(cosb, sinb);
    attn_mma<<<dim3(4, NHEAD, NPAIR), 256, ASMEM>>>(p0h, p0l);

    // 5. tmp = att @ o_w^T  (K=512, N=512)
    gemm_mma<<<dim3(4, HSUB / 128, NPAIR), 256, 3 * STG>>>(
        p0h, p0l, 1, p_wh + OFF_O, p_wl + OFF_O, p_tmp, HSUB, HSUB,
        (unsigned short*)0, (unsigned short*)0, 0);

    // 6. hs1 = rmsnorm(hs0 + tmp) -> planes P1
    resnorm2_kernel<<<NPAIR * Ss / 8, 256>>>(p1h, p1l);

    // 7+8. act = silu(gate)*up fused into gu GEMM epilogue (smem-staged) -> planes P0
    gemm_mma<<<dim3(4, GUW / 128, NPAIR), 256, 3 * STG>>>(
        p1h, p1l, 1, p_wh + OFF_GU, p_wl + OFF_GU, (float*)0, HSUB, GUW, p0h, p0l, 2);

    // 9. tmp = act @ mlp_down_w^T  (K=1536, N=512)
    gemm_mma<<<dim3(4, HSUB / 128, NPAIR), 256, 3 * STG>>>(
        p0h, p0l, 1, p_wh + OFF_MLPD, p_wl + OFF_MLPD, p_tmp, INTER, HSUB,
        (unsigned short*)0, (unsigned short*)0, 0);

    // 10. hs2 = rmsnorm(hs1 + tmp) -> planes P1
    resnorm2_kernel<<<NPAIR * Ss / 8, 256>>>(p1h, p1l);

    // 11. up_out = hs2 @ up_w^T  (K=512, N=1024)
    gemm_mma<<<dim3(4, Hh / 128, NPAIR), 256, 3 * STG>>>(
        p1h, p1l, 1, p_wh + OFF_UP, p_wl + OFF_UP, p_up, HSUB, Hh,
        (unsigned short*)0, (unsigned short*)0, 0);

    // 12. out = rmsnorm(h + w0*u0 + w1*u1), warp-per-row
    final_kernel<<<Bb * Ss / 8, 256>>>(out);
}